// round 15
// baseline (speedup 1.0000x reference)
#include <cuda_runtime.h>
#include <cuda_bf16.h>
#include <math.h>
#include <stdint.h>

// ---------------------------------------------------------------------------
// Problem constants
// ---------------------------------------------------------------------------
#define D_    1024
#define HD_   128
#define EA_   8
#define EF_   16
#define FH_   512
#define S_    1024
#define B_    4
#define NTOK_ 4096
#define NTS_  8192
#define CAP_  4096

#define WSEG_W1 0
#define WSEG_W2 8388608
#define WSEG_QW 16777216
#define WSEG_OW 17825792
#define WSEG_KW 18874368
#define WSEG_VW 19005440
#define WSEG_END 19136512

// ---------------------------------------------------------------------------
// PTX helpers
// ---------------------------------------------------------------------------
__device__ __forceinline__ uint32_t smem_to_u32(const void* p) {
    uint32_t a;
    asm("{ .reg .u64 t; cvta.to.shared.u64 t, %1; cvt.u32.u64 %0, t; }"
        : "=r"(a) : "l"(p));
    return a;
}
__device__ __forceinline__ void ldsm4(uint32_t& r0, uint32_t& r1,
                                      uint32_t& r2, uint32_t& r3, uint32_t a) {
    asm volatile("ldmatrix.sync.aligned.m8n8.x4.shared.b16 {%0,%1,%2,%3}, [%4];"
                 : "=r"(r0), "=r"(r1), "=r"(r2), "=r"(r3) : "r"(a));
}
__device__ __forceinline__ void ldsm4t(uint32_t& r0, uint32_t& r1,
                                       uint32_t& r2, uint32_t& r3, uint32_t a) {
    asm volatile("ldmatrix.sync.aligned.m8n8.x4.trans.shared.b16 {%0,%1,%2,%3}, [%4];"
                 : "=r"(r0), "=r"(r1), "=r"(r2), "=r"(r3) : "r"(a));
}
__device__ __forceinline__ void mma16816(float* c, const uint32_t* a,
                                         const uint32_t* b) {
    asm volatile(
        "mma.sync.aligned.m16n8k16.row.col.f32.bf16.bf16.f32 "
        "{%0,%1,%2,%3}, {%4,%5,%6,%7}, {%8,%9}, {%0,%1,%2,%3};"
        : "+f"(c[0]), "+f"(c[1]), "+f"(c[2]), "+f"(c[3])
        : "r"(a[0]), "r"(a[1]), "r"(a[2]), "r"(a[3]), "r"(b[0]), "r"(b[1]));
}
__device__ __forceinline__ uint32_t packbf(float a, float b) {
    __nv_bfloat162 p = __floats2bfloat162_rn(a, b);
    return *(uint32_t*)&p;
}
#define CPASYNC16(dst, src) \
    asm volatile("cp.async.cg.shared.global [%0], [%1], 16;" \
                 :: "r"(dst), "l"(src))
#define CPCOMMIT() asm volatile("cp.async.commit_group;" ::: "memory")
#define CPWAIT2()  asm volatile("cp.async.wait_group 2;" ::: "memory")
#define CPWAIT1()  asm volatile("cp.async.wait_group 1;" ::: "memory")
#define CPWAIT0()  asm volatile("cp.async.wait_group 0;" ::: "memory")

// ---------------------------------------------------------------------------
// Device-global scratch
// ---------------------------------------------------------------------------
__device__ float g_gwa [NTS_];
__device__ float g_gwf [NTS_];
__device__ int   g_cnt_a [EA_];
__device__ int   g_cnt_f [EF_];
__device__ int   g_list_a[EA_ * CAP_];
__device__ int   g_list_f[EF_ * CAP_];
__device__ int   g_list_id[CAP_];
__device__ float g_kvb [2 * HD_];
__device__ __nv_bfloat16 g_xn_bf [NTOK_ * D_];
__device__ __nv_bfloat16 g_xn2_bf[NTOK_ * D_];
__device__ __nv_bfloat16 g_q_bf  [NTS_  * HD_];
__device__ __nv_bfloat16 g_kv_bf [2 * NTOK_ * HD_];
__device__ __nv_bfloat16 g_ctx_bf[NTS_  * HD_];
__device__ __nv_bfloat16 g_h_bf  [NTS_  * FH_];
__device__ __nv_bfloat16 g_ya_bf [NTS_  * D_];
__device__ __nv_bfloat16 g_wbf [WSEG_END];

// ---------------------------------------------------------------------------
// Setup
// ---------------------------------------------------------------------------
__global__ void __launch_bounds__(256) setup_k(const float* __restrict__ kb,
                                               const float* __restrict__ vb) {
    int i = blockIdx.x * 256 + threadIdx.x;
    if (i < EA_) g_cnt_a[i] = 0;
    if (i < EF_) g_cnt_f[i] = 0;
    if (i < CAP_) g_list_id[i] = i;
    if (i < HD_) g_kvb[i] = kb[i];
    else if (i >= CAP_ && i < CAP_ + HD_) g_kvb[HD_ + i - CAP_] = vb[i - CAP_];
}

// ---------------------------------------------------------------------------
// Flat fp32->bf16 weight convert
// ---------------------------------------------------------------------------
__global__ void __launch_bounds__(256) conv_all_k(
    const float* __restrict__ w1, const float* __restrict__ w2,
    const float* __restrict__ qw, const float* __restrict__ ow,
    const float* __restrict__ kw, const float* __restrict__ vw)
{
    size_t el = ((size_t)blockIdx.x * 256 + threadIdx.x) * 4;
    if (el >= WSEG_END) return;
    const float* src;
    if (el < WSEG_W2)      src = w1 + (el - WSEG_W1);
    else if (el < WSEG_QW) src = w2 + (el - WSEG_W2);
    else if (el < WSEG_OW) src = qw + (el - WSEG_QW);
    else if (el < WSEG_KW) src = ow + (el - WSEG_OW);
    else if (el < WSEG_VW) src = kw + (el - WSEG_KW);
    else                   src = vw + (el - WSEG_VW);
    float4 v = *(const float4*)src;
    uint2 st;
    st.x = packbf(v.x, v.y); st.y = packbf(v.z, v.w);
    *(uint2*)(g_wbf + el) = st;
}

// ---------------------------------------------------------------------------
// LayerNorm 1 + attention router fused
// ---------------------------------------------------------------------------
__global__ void __launch_bounds__(256) ln1_k(
    const float* __restrict__ x, const float* __restrict__ w,
    const float* __restrict__ b, const float* __restrict__ gwm,
    __nv_bfloat16* __restrict__ ybf)
{
    int t = blockIdx.x, tid = threadIdx.x;
    int lane = tid & 31, wrp = tid >> 5;
    float4 v = ((const float4*)(x + (size_t)t * D_))[tid];
    float s = v.x + v.y + v.z + v.w;
    float q = fmaf(v.x, v.x, fmaf(v.y, v.y, fmaf(v.z, v.z, v.w * v.w)));
    __shared__ float ss[8], sq[8];
    __shared__ float sp[8][EA_];
    #pragma unroll
    for (int o = 16; o; o >>= 1) {
        s += __shfl_xor_sync(0xffffffffu, s, o);
        q += __shfl_xor_sync(0xffffffffu, q, o);
    }
    if (lane == 0) { ss[wrp] = s; sq[wrp] = q; }
    __syncthreads();
    if (tid == 0) {
        float a = 0.f, c = 0.f;
        #pragma unroll
        for (int i = 0; i < 8; i++) { a += ss[i]; c += sq[i]; }
        ss[0] = a; sq[0] = c;
    }
    __syncthreads();
    float mu  = ss[0] * (1.f / D_);
    float var = sq[0] * (1.f / D_) - mu * mu;
    float rs  = rsqrtf(var + 1e-5f);
    float4 wv = ((const float4*)w)[tid];
    float4 bv = ((const float4*)b)[tid];
    float o0 = (v.x - mu) * rs * wv.x + bv.x;
    float o1 = (v.y - mu) * rs * wv.y + bv.y;
    float o2 = (v.z - mu) * rs * wv.z + bv.z;
    float o3 = (v.w - mu) * rs * wv.w + bv.w;
    uint2 st;
    st.x = packbf(o0, o1); st.y = packbf(o2, o3);
    *(uint2*)(ybf + (size_t)t * D_ + tid * 4) = st;

    float p[EA_];
    #pragma unroll
    for (int e = 0; e < EA_; e++) p[e] = 0.f;
    float xs[4] = {o0, o1, o2, o3};
    const float4* g4 = (const float4*)(gwm + (size_t)(tid * 4) * EA_);
    #pragma unroll
    for (int j = 0; j < 4; j++) {
        float4 ga = g4[j * 2], gb = g4[j * 2 + 1];
        p[0] = fmaf(xs[j], ga.x, p[0]); p[1] = fmaf(xs[j], ga.y, p[1]);
        p[2] = fmaf(xs[j], ga.z, p[2]); p[3] = fmaf(xs[j], ga.w, p[3]);
        p[4] = fmaf(xs[j], gb.x, p[4]); p[5] = fmaf(xs[j], gb.y, p[5]);
        p[6] = fmaf(xs[j], gb.z, p[6]); p[7] = fmaf(xs[j], gb.w, p[7]);
    }
    #pragma unroll
    for (int e = 0; e < EA_; e++)
        #pragma unroll
        for (int o = 16; o; o >>= 1)
            p[e] += __shfl_xor_sync(0xffffffffu, p[e], o);
    if (lane == 0)
        #pragma unroll
        for (int e = 0; e < EA_; e++) sp[wrp][e] = p[e];
    __syncthreads();
    if (tid == 0) {
        float l[EA_];
        #pragma unroll
        for (int e = 0; e < EA_; e++) {
            float a = 0.f;
            #pragma unroll
            for (int wdx = 0; wdx < 8; wdx++) a += sp[wdx][e];
            l[e] = a;
        }
        int i0 = 0; float v0 = l[0];
        #pragma unroll
        for (int e = 1; e < EA_; e++) if (l[e] > v0) { v0 = l[e]; i0 = e; }
        int i1 = -1; float v1 = -1e30f;
        #pragma unroll
        for (int e = 0; e < EA_; e++)
            if (e != i0 && l[e] > v1) { v1 = l[e]; i1 = e; }
        float e1 = __expf(v1 - v0);
        float inv = 1.f / (1.f + e1);
        g_gwa[2 * t]     = inv;
        g_gwa[2 * t + 1] = e1 * inv;
        int p0 = atomicAdd(&g_cnt_a[i0], 1);
        g_list_a[i0 * CAP_ + p0] = 2 * t;
        int p1 = atomicAdd(&g_cnt_a[i1], 1);
        g_list_a[i1 * CAP_ + p1] = 2 * t + 1;
    }
}

// ---------------------------------------------------------------------------
// Residual-add (ya bf16) + LayerNorm 2 + FFN router fused; residual -> out
// ---------------------------------------------------------------------------
__global__ void __launch_bounds__(256) combine_ln2_k(
    const float* __restrict__ src, const __nv_bfloat16* __restrict__ ya,
    const float* __restrict__ w, const float* __restrict__ b,
    const float* __restrict__ gwm,
    float* __restrict__ out, __nv_bfloat16* __restrict__ xn2bf)
{
    int t = blockIdx.x, tid = threadIdx.x;
    int lane = tid & 31, wrp = tid >> 5;
    float4 v  = ((const float4*)(src + (size_t)t * D_))[tid];
    uint2 u0 = *(const uint2*)(ya + (size_t)(2 * t) * D_ + tid * 4);
    uint2 u1 = *(const uint2*)(ya + (size_t)(2 * t + 1) * D_ + tid * 4);
    {
        __nv_bfloat162 a0 = *(__nv_bfloat162*)&u0.x;
        __nv_bfloat162 a1 = *(__nv_bfloat162*)&u0.y;
        __nv_bfloat162 b0 = *(__nv_bfloat162*)&u1.x;
        __nv_bfloat162 b1 = *(__nv_bfloat162*)&u1.y;
        v.x += __bfloat162float(a0.x) + __bfloat162float(b0.x);
        v.y += __bfloat162float(a0.y) + __bfloat162float(b0.y);
        v.z += __bfloat162float(a1.x) + __bfloat162float(b1.x);
        v.w += __bfloat162float(a1.y) + __bfloat162float(b1.y);
    }
    ((float4*)(out + (size_t)t * D_))[tid] = v;

    float s = v.x + v.y + v.z + v.w;
    float q = fmaf(v.x, v.x, fmaf(v.y, v.y, fmaf(v.z, v.z, v.w * v.w)));
    __shared__ float ss[8], sq[8];
    __shared__ float sp[8][EF_];
    #pragma unroll
    for (int o = 16; o; o >>= 1) {
        s += __shfl_xor_sync(0xffffffffu, s, o);
        q += __shfl_xor_sync(0xffffffffu, q, o);
    }
    if (lane == 0) { ss[wrp] = s; sq[wrp] = q; }
    __syncthreads();
    if (tid == 0) {
        float a = 0.f, c = 0.f;
        #pragma unroll
        for (int i = 0; i < 8; i++) { a += ss[i]; c += sq[i]; }
        ss[0] = a; sq[0] = c;
    }
    __syncthreads();
    float mu  = ss[0] * (1.f / D_);
    float var = sq[0] * (1.f / D_) - mu * mu;
    float rs  = rsqrtf(var + 1e-5f);
    float4 wv = ((const float4*)w)[tid];
    float4 bv = ((const float4*)b)[tid];
    float o0 = (v.x - mu) * rs * wv.x + bv.x;
    float o1 = (v.y - mu) * rs * wv.y + bv.y;
    float o2 = (v.z - mu) * rs * wv.z + bv.z;
    float o3 = (v.w - mu) * rs * wv.w + bv.w;
    uint2 st;
    st.x = packbf(o0, o1); st.y = packbf(o2, o3);
    *(uint2*)(xn2bf + (size_t)t * D_ + tid * 4) = st;

    float p[EF_];
    #pragma unroll
    for (int e = 0; e < EF_; e++) p[e] = 0.f;
    float xs[4] = {o0, o1, o2, o3};
    const float4* g4 = (const float4*)(gwm + (size_t)(tid * 4) * EF_);
    #pragma unroll
    for (int j = 0; j < 4; j++) {
        #pragma unroll
        for (int g = 0; g < 4; g++) {
            float4 gv = g4[j * 4 + g];
            p[g*4+0] = fmaf(xs[j], gv.x, p[g*4+0]);
            p[g*4+1] = fmaf(xs[j], gv.y, p[g*4+1]);
            p[g*4+2] = fmaf(xs[j], gv.z, p[g*4+2]);
            p[g*4+3] = fmaf(xs[j], gv.w, p[g*4+3]);
        }
    }
    #pragma unroll
    for (int e = 0; e < EF_; e++)
        #pragma unroll
        for (int o = 16; o; o >>= 1)
            p[e] += __shfl_xor_sync(0xffffffffu, p[e], o);
    if (lane == 0)
        #pragma unroll
        for (int e = 0; e < EF_; e++) sp[wrp][e] = p[e];
    __syncthreads();
    if (tid == 0) {
        float l[EF_];
        #pragma unroll
        for (int e = 0; e < EF_; e++) {
            float a = 0.f;
            #pragma unroll
            for (int wdx = 0; wdx < 8; wdx++) a += sp[wdx][e];
            l[e] = a;
        }
        int i0 = 0; float v0 = l[0];
        #pragma unroll
        for (int e = 1; e < EF_; e++) if (l[e] > v0) { v0 = l[e]; i0 = e; }
        int i1 = -1; float v1 = -1e30f;
        #pragma unroll
        for (int e = 0; e < EF_; e++)
            if (e != i0 && l[e] > v1) { v1 = l[e]; i1 = e; }
        float e1 = __expf(v1 - v0);
        float inv = 1.f / (1.f + e1);
        g_gwf[2 * t]     = inv;
        g_gwf[2 * t + 1] = e1 * inv;
        int p0 = atomicAdd(&g_cnt_f[i0], 1);
        g_list_f[i0 * CAP_ + p0] = 2 * t;
        int p1 = atomicAdd(&g_cnt_f[i1], 1);
        g_list_f[i1 * CAP_ + p1] = 2 * t + 1;
    }
}

// ---------------------------------------------------------------------------
// Generic grouped GEMM, 4-stage cp.async ring, ONE barrier per stage.
// ---------------------------------------------------------------------------
#define LDAB 72
#define LDB_ 136

template<int KTOT, int BM, bool TOKROW, bool RELU, bool GATE, bool OUTBF, bool ACCUM>
__global__ void __launch_bounds__(256) mmasync_gemm_k(
    const __nv_bfloat16* __restrict__ Abase,
    const __nv_bfloat16* __restrict__ Bbase,
    const float* __restrict__ biasb, int Nfull,
    void* __restrict__ Yv, int ldy, size_t eStrideY,
    const int* __restrict__ lists, const int* __restrict__ cnts,
    const float* __restrict__ gw, float scale)
{
    constexpr int MWARPS = BM / 32;
    constexpr int NWARPS = 8 / MWARPS;
    constexpr int WN     = 128 / NWARPS;
    constexpr int NT     = WN / 8;
    constexpr int A_CH   = BM * 8 / 256;
    constexpr int ASTG   = BM * LDAB * 2;
    constexpr int STAGE  = ASTG + 64 * LDB_ * 2;

    int e = blockIdx.z;
    int cnt = cnts[e];
    int row0 = blockIdx.y * BM;
    if (row0 >= cnt) return;
    int n0 = blockIdx.x * 128;
    const int* list = lists + e * CAP_;

    extern __shared__ char dynsm[];
    __shared__ float bias_s[128];
    __shared__ float gate_s[BM];
    __shared__ int   slot_s[BM];

    int tid = threadIdx.x;
    int wid = tid >> 5, lane = tid & 31;

    if (tid < 128) bias_s[tid] = biasb[(size_t)e * Nfull + n0 + tid];
    if (tid < BM) {
        int r = min(row0 + tid, cnt - 1);
        int sl = list[r];
        slot_s[tid] = sl;
        gate_s[tid] = GATE ? gw[sl] : 1.f;
    }

    uint32_t sBase = smem_to_u32(dynsm);
    uint32_t sA0 = sBase;
    uint32_t sB0 = sBase + ASTG;

    const __nv_bfloat16* Bexp = Bbase + (size_t)e * Nfull * KTOT;
    const __nv_bfloat16* aSrc[A_CH];
    uint32_t aDst[A_CH];
    #pragma unroll
    for (int i = 0; i < A_CH; i++) {
        int idx = tid + i * 256;
        int am = idx >> 3, ac = idx & 7;
        int r = min(row0 + am, cnt - 1);
        int sl = list[r];
        int gr = TOKROW ? (sl >> 1) : sl;
        aSrc[i] = Abase + (size_t)gr * KTOT + ac * 8;
        aDst[i] = sA0 + (am * LDAB + ac * 8) * 2;
    }
    const __nv_bfloat16* bSrc[4];
    uint32_t bDst[4];
    #pragma unroll
    for (int i = 0; i < 4; i++) {
        int idx = tid + i * 256;
        int bk = idx >> 4, bn = (idx & 15) * 8;
        bSrc[i] = Bexp + (size_t)bk * Nfull + n0 + bn;
        bDst[i] = sB0 + (bk * LDB_ + bn) * 2;
    }

    int warpM = (wid % MWARPS) * 32;
    int warpN = (wid / MWARPS) * WN;
    uint32_t aAddr = sA0 + ((warpM + (lane & 15)) * LDAB + (lane >> 4) * 8) * 2;
    uint32_t bAddrBase = sB0 + ((lane & 15) * LDB_ + warpN + (lane >> 4) * 8) * 2;

    float acc[2][NT][4];
    #pragma unroll
    for (int mt = 0; mt < 2; mt++)
        #pragma unroll
        for (int nt = 0; nt < NT; nt++)
            #pragma unroll
            for (int j = 0; j < 4; j++) acc[mt][nt][j] = 0.f;

    const int NSTAGE = KTOT / 64;

    // prologue: stages 0,1,2
    #pragma unroll
    for (int i = 0; i < A_CH; i++) CPASYNC16(aDst[i], aSrc[i]);
    #pragma unroll
    for (int i = 0; i < 4; i++) CPASYNC16(bDst[i], bSrc[i]);
    CPCOMMIT();
    if (NSTAGE > 1) {
        #pragma unroll
        for (int i = 0; i < A_CH; i++) CPASYNC16(aDst[i] + STAGE, aSrc[i] + 64);
        #pragma unroll
        for (int i = 0; i < 4; i++)
            CPASYNC16(bDst[i] + STAGE, bSrc[i] + (size_t)64 * Nfull);
        CPCOMMIT();
    }
    if (NSTAGE > 2) {
        #pragma unroll
        for (int i = 0; i < A_CH; i++) CPASYNC16(aDst[i] + 2 * STAGE, aSrc[i] + 128);
        #pragma unroll
        for (int i = 0; i < 4; i++)
            CPASYNC16(bDst[i] + 2 * STAGE, bSrc[i] + (size_t)128 * Nfull);
        CPCOMMIT();
    }

    for (int st = 0; st < NSTAGE; st++) {
        if (st + 2 < NSTAGE) CPWAIT2();
        else if (st + 1 < NSTAGE) CPWAIT1();
        else CPWAIT0();
        __syncthreads();
        uint32_t off = (st & 3) * STAGE;
        #pragma unroll
        for (int kk = 0; kk < 4; kk++) {
            uint32_t a[2][4];
            ldsm4(a[0][0], a[0][1], a[0][2], a[0][3], aAddr + off + kk * 32);
            ldsm4(a[1][0], a[1][1], a[1][2], a[1][3],
                  aAddr + off + 16 * LDAB * 2 + kk * 32);
            uint32_t b[NT][2];
            #pragma unroll
            for (int np = 0; np < NT / 2; np++) {
                uint32_t r0, r1, r2, r3;
                ldsm4t(r0, r1, r2, r3,
                       bAddrBase + off + kk * (16 * LDB_ * 2) + np * 32);
                b[np * 2][0] = r0;     b[np * 2][1] = r1;
                b[np * 2 + 1][0] = r2; b[np * 2 + 1][1] = r3;
            }
            #pragma unroll
            for (int mt = 0; mt < 2; mt++)
                #pragma unroll
                for (int nt = 0; nt < NT; nt++)
                    mma16816(acc[mt][nt], a[mt], b[nt]);
        }
        // prefetch st+3 AFTER compute: buffer (st+3)&3 = (st-1)&3 whose
        // readers finished before this iteration's barrier.
        if (st + 3 < NSTAGE) {
            uint32_t boff = ((st + 3) & 3) * STAGE;
            int k0 = (st + 3) * 64;
            #pragma unroll
            for (int i = 0; i < A_CH; i++) CPASYNC16(aDst[i] + boff, aSrc[i] + k0);
            #pragma unroll
            for (int i = 0; i < 4; i++)
                CPASYNC16(bDst[i] + boff, bSrc[i] + (size_t)k0 * Nfull);
            CPCOMMIT();
        }
    }

    int lane4 = lane >> 2;
    int lcol  = (lane & 3) * 2;
    #pragma unroll
    for (int mt = 0; mt < 2; mt++) {
        #pragma unroll
        for (int h = 0; h < 2; h++) {
            int m = warpM + mt * 16 + lane4 + h * 8;
            if (row0 + m >= cnt) continue;
            int sl = slot_s[m];
            float f = gate_s[m];
            int orow = ACCUM ? (sl >> 1) : sl;
            size_t ybase = (size_t)e * eStrideY + (size_t)orow * ldy + n0;
            #pragma unroll
            for (int nt = 0; nt < NT; nt++) {
                int col = warpN + nt * 8 + lcol;
                float v0 = (acc[mt][nt][h * 2 + 0] + bias_s[col]) * scale;
                float v1 = (acc[mt][nt][h * 2 + 1] + bias_s[col + 1]) * scale;
                if (RELU) { v0 = fmaxf(v0, 0.f); v1 = fmaxf(v1, 0.f); }
                v0 *= f; v1 *= f;
                if (ACCUM) {
                    atomicAdd((float*)Yv + ybase + col, v0);
                    atomicAdd((float*)Yv + ybase + col + 1, v1);
                } else if (OUTBF) {
                    *(uint32_t*)((__nv_bfloat16*)Yv + ybase + col) = packbf(v0, v1);
                } else {
                    float2 p = make_float2(v0, v1);
                    *(float2*)((float*)Yv + ybase + col) = p;
                }
            }
        }
    }
}

#define GEMM_SMEM_BM64  (4 * (64 * LDAB * 2 + 64 * LDB_ * 2))
#define GEMM_SMEM_BM128 (4 * (128 * LDAB * 2 + 64 * LDB_ * 2))

// ---------------------------------------------------------------------------
// Fused K/V + Q projection — 4-stage ring, ONE barrier per stage
// ---------------------------------------------------------------------------
__global__ void __launch_bounds__(256) qkv_k(
    const __nv_bfloat16* __restrict__ Abase,
    const __nv_bfloat16* __restrict__ kvw,
    const __nv_bfloat16* __restrict__ qwv,
    const float* __restrict__ kvb2,
    const float* __restrict__ qb,
    __nv_bfloat16* __restrict__ kvout,
    __nv_bfloat16* __restrict__ qout,
    const int* __restrict__ lista,
    const int* __restrict__ cnta,
    float qscale)
{
    constexpr int BM = 64, NT = 4;
    constexpr int ASTG  = BM * LDAB * 2;
    constexpr int STAGE = ASTG + 64 * LDB_ * 2;
    const int KTOT = D_, NSTAGE = D_ / 64;

    int z = blockIdx.z;
    bool isQ = (z >= 2);
    int e = isQ ? (z - 2) : z;
    int cnt = isQ ? cnta[e] : NTOK_;
    int row0 = blockIdx.y * BM;
    if (row0 >= cnt) return;
    const int* list = isQ ? (lista + e * CAP_) : g_list_id;
    const __nv_bfloat16* Bexp = (isQ ? qwv : kvw) + (size_t)e * HD_ * D_;
    const float* bias = (isQ ? qb : kvb2) + (size_t)e * HD_;
    float scale = isQ ? qscale : 1.f;
    __nv_bfloat16* Yp = isQ ? qout : (kvout + (size_t)e * NTOK_ * HD_);

    extern __shared__ char dynsm[];
    __shared__ float bias_s[128];
    __shared__ int   slot_s[BM];

    int tid = threadIdx.x;
    int wid = tid >> 5, lane = tid & 31;

    if (tid < 128) bias_s[tid] = bias[tid];
    if (tid < BM) {
        int r = min(row0 + tid, cnt - 1);
        slot_s[tid] = list[r];
    }

    uint32_t sBase = smem_to_u32(dynsm);
    uint32_t sA0 = sBase;
    uint32_t sB0 = sBase + ASTG;

    const __nv_bfloat16* aSrc[2];
    uint32_t aDst[2];
    #pragma unroll
    for (int i = 0; i < 2; i++) {
        int idx = tid + i * 256;
        int am = idx >> 3, ac = idx & 7;
        int r = min(row0 + am, cnt - 1);
        int sl = list[r];
        int gr = isQ ? (sl >> 1) : sl;
        aSrc[i] = Abase + (size_t)gr * KTOT + ac * 8;
        aDst[i] = sA0 + (am * LDAB + ac * 8) * 2;
    }
    const __nv_bfloat16* bSrc[4];
    uint32_t bDst[4];
    #pragma unroll
    for (int i = 0; i < 4; i++) {
        int idx = tid + i * 256;
        int bk = idx >> 4, bn = (idx & 15) * 8;
        bSrc[i] = Bexp + (size_t)bk * HD_ + bn;
        bDst[i] = sB0 + (bk * LDB_ + bn) * 2;
    }

    int warpM = (wid & 1) * 32;
    int warpN = (wid >> 1) * 32;
    uint32_t aAddr = sA0 + ((warpM + (lane & 15)) * LDAB + (lane >> 4) * 8) * 2;
    uint32_t bAddrBase = sB0 + ((lane & 15) * LDB_ + warpN + (lane >> 4) * 8) * 2;

    float acc[2][NT][4];
    #pragma unroll
    for (int mt = 0; mt < 2; mt++)
        #pragma unroll
        for (int nt = 0; nt < NT; nt++)
            #pragma unroll
            for (int j = 0; j < 4; j++) acc[mt][nt][j] = 0.f;

    // prologue: stages 0,1,2
    #pragma unroll
    for (int i = 0; i < 2; i++) CPASYNC16(aDst[i], aSrc[i]);
    #pragma unroll
    for (int i = 0; i < 4; i++) CPASYNC16(bDst[i], bSrc[i]);
    CPCOMMIT();
    #pragma unroll
    for (int i = 0; i < 2; i++) CPASYNC16(aDst[i] + STAGE, aSrc[i] + 64);
    #pragma unroll
    for (int i = 0; i < 4; i++)
        CPASYNC16(bDst[i] + STAGE, bSrc[i] + (size_t)64 * HD_);
    CPCOMMIT();
    #pragma unroll
    for (int i = 0; i < 2; i++) CPASYNC16(aDst[i] + 2 * STAGE, aSrc[i] + 128);
    #pragma unroll
    for (int i = 0; i < 4; i++)
        CPASYNC16(bDst[i] + 2 * STAGE, bSrc[i] + (size_t)128 * HD_);
    CPCOMMIT();

    for (int st = 0; st < NSTAGE; st++) {
        if (st + 2 < NSTAGE) CPWAIT2();
        else if (st + 1 < NSTAGE) CPWAIT1();
        else CPWAIT0();
        __syncthreads();
        uint32_t off = (st & 3) * STAGE;
        #pragma unroll
        for (int kk = 0; kk < 4; kk++) {
            uint32_t a[2][4];
            ldsm4(a[0][0], a[0][1], a[0][2], a[0][3], aAddr + off + kk * 32);
            ldsm4(a[1][0], a[1][1], a[1][2], a[1][3],
                  aAddr + off + 16 * LDAB * 2 + kk * 32);
            uint32_t b[NT][2];
            #pragma unroll
            for (int np = 0; np < NT / 2; np++) {
                uint32_t r0, r1, r2, r3;
                ldsm4t(r0, r1, r2, r3,
                       bAddrBase + off + kk * (16 * LDB_ * 2) + np * 32);
                b[np * 2][0] = r0;     b[np * 2][1] = r1;
                b[np * 2 + 1][0] = r2; b[np * 2 + 1][1] = r3;
            }
            #pragma unroll
            for (int mt = 0; mt < 2; mt++)
                #pragma unroll
                for (int nt = 0; nt < NT; nt++)
                    mma16816(acc[mt][nt], a[mt], b[nt]);
        }
        if (st + 3 < NSTAGE) {
            uint32_t boff = ((st + 3) & 3) * STAGE;
            int k0 = (st + 3) * 64;
            #pragma unroll
            for (int i = 0; i < 2; i++) CPASYNC16(aDst[i] + boff, aSrc[i] + k0);
            #pragma unroll
            for (int i = 0; i < 4; i++)
                CPASYNC16(bDst[i] + boff, bSrc[i] + (size_t)k0 * HD_);
            CPCOMMIT();
        }
    }

    int lane4 = lane >> 2;
    int lcol  = (lane & 3) * 2;
    #pragma unroll
    for (int mt = 0; mt < 2; mt++) {
        #pragma unroll
        for (int h = 0; h < 2; h++) {
            int m = warpM + mt * 16 + lane4 + h * 8;
            if (row0 + m >= cnt) continue;
            int sl = slot_s[m];
            #pragma unroll
            for (int nt = 0; nt < NT; nt++) {
                int col = warpN + nt * 8 + lcol;
                float v0 = (acc[mt][nt][h * 2 + 0] + bias_s[col]) * scale;
                float v1 = (acc[mt][nt][h * 2 + 1] + bias_s[col + 1]) * scale;
                *(uint32_t*)(Yp + (size_t)sl * HD_ + col) = packbf(v0, v1);
            }
        }
    }
}

// ---------------------------------------------------------------------------
// Tensor-core flash attention — K/V cp.async double-buffered (unchanged)
// ---------------------------------------------------------------------------
#define ATT2_QS   0
#define ATT2_KS   17408
#define ATT2_VS   87040
#define ATT2_RL   156672
#define ATT2_SM   190464
#define ATT2_SL   190976
#define ATT2_SMEM 191488
#define ATT_WGS   34816
#define ATT_BUFS  17408

__global__ void __launch_bounds__(256) attn_mma_k(
    const __nv_bfloat16* __restrict__ qg,
    const __nv_bfloat16* __restrict__ kg,
    const __nv_bfloat16* __restrict__ vg,
    const float* __restrict__ rel,
    __nv_bfloat16* __restrict__ ctxg)
{
    extern __shared__ char smraw[];
    __nv_bfloat16* Qs = (__nv_bfloat16*)(smraw + ATT2_QS);
    float* Rl = (float*)(smraw + ATT2_RL);
    float* sM = (float*)(smraw + ATT2_SM);
    float* sL = (float*)(smraw + ATT2_SL);

    int tid = threadIdx.x;
    int wid = tid >> 5, lane = tid & 31;
    int wg = wid >> 2, ww = wid & 3;
    int t128 = tid & 127;

    int gs0 = blockIdx.x * 64;
    int b   = gs0 >> 11;
    int ls0 = gs0 & 2047;

    {
        int r = tid >> 2, cb = (tid & 3) * 32;
        const uint4* src = (const uint4*)(qg + (size_t)(gs0 + r) * HD_ + cb);
        uint4* dst = (uint4*)(smraw + ATT2_QS + r * 272 + cb * 2);
        #pragma unroll
        for (int i = 0; i < 4; i++) dst[i] = src[i];
    }
    {
        int r = t128 >> 1, cb = (t128 & 1) * 64;
        int rr = wg * 64 + r;
        const float* src = rel + (size_t)rr * HD_ + cb;
        char* dst = smraw + ATT2_KS + wg * ATT_WGS + r * 272 + cb * 2;
        #pragma unroll
        for (int i = 0; i < 8; i++) {
            float4 f0 = *(const float4*)(src + i * 8);
            float4 f1 = *(const float4*)(src + i * 8 + 4);
            uint4 st;
            st.x = packbf(f0.x, f0.y); st.y = packbf(f0.z, f0.w);
            st.z = packbf(f1.x, f1.y); st.w = packbf(f1.z, f1.w);
            *(uint4*)(dst + i * 16) = st;
        }
    }
    __syncthreads();

    uint32_t sQ = smem_to_u32(smraw + ATT2_QS);
    uint32_t aQAddr = sQ + (ww * 16 + (lane & 15)) * 272 + (lane >> 4) * 16;
    uint32_t qf[8][4];
    #pragma unroll
    for (int ks = 0; ks < 8; ks++)
        ldsm4(qf[ks][0], qf[ks][1], qf[ks][2], qf[ks][3], aQAddr + ks * 32);

    int bRow = ((lane >> 4) & 1) * 8 + (lane & 7);
    int bColB = ((lane >> 3) & 1) * 16;
    uint32_t sKS = smem_to_u32(smraw + ATT2_KS) + wg * ATT_WGS;
    uint32_t sVS = smem_to_u32(smraw + ATT2_VS) + wg * ATT_WGS;

    int r0 = lane >> 2, cA = (lane & 3) * 2;
    int m0row = ww * 16 + r0;

    {
        float c[8][4];
        #pragma unroll
        for (int nt = 0; nt < 8; nt++)
            #pragma unroll
            for (int j = 0; j < 4; j++) c[nt][j] = 0.f;
        #pragma unroll
        for (int ks = 0; ks < 8; ks++) {
            uint32_t bfd[8][2];
            #pragma unroll
            for (int np = 0; np < 4; np++) {
                uint32_t x0, x1, x2, x3;
                ldsm4(x0, x1, x2, x3,
                      sKS + (np * 16 + bRow) * 272 + bColB + ks * 32);
                bfd[np * 2][0] = x0;     bfd[np * 2][1] = x1;
                bfd[np * 2 + 1][0] = x2; bfd[np * 2 + 1][1] = x3;
            }
            #pragma unroll
            for (int nt = 0; nt < 8; nt++)
                mma16816(c[nt], qf[ks], bfd[nt]);
        }
        #pragma unroll
        for (int nt = 0; nt < 8; nt++) {
            int col = wg * 64 + nt * 8 + cA;
            Rl[m0row * 132 + col]           = c[nt][0];
            Rl[m0row * 132 + col + 1]       = c[nt][1];
            Rl[(m0row + 8) * 132 + col]     = c[nt][2];
            Rl[(m0row + 8) * 132 + col + 1] = c[nt][3];
        }
    }
    {
        int m = tid >> 2, l4 = tid & 3;
        const float* rrow = rel + (size_t)128 * HD_ + l4 * 32;
        const __nv_bfloat16* qrow = Qs + m * 136 + l4 * 32;
        float s = 0.f;
        #pragma unroll
        for (int i = 0; i < 32; i++)
            s = fmaf(__bfloat162float(qrow[i]), rrow[i], s);
        s += __shfl_xor_sync(0xffffffffu, s, 1);
        s += __shfl_xor_sync(0xffffffffu, s, 2);
        if (l4 == 0) Rl[m * 132 + 128] = s;
    }
    __syncthreads();

    float m_run0 = -1e30f, m_run1 = -1e30f;
    float l_run0 = 0.f, l_run1 = 0.f;
    float ctx[16][4];
    #pragma unroll
    for (int nt = 0; nt < 16; nt++)
        #pragma unroll
        for (int j = 0; j < 4; j++) ctx[nt][j] = 0.f;

    int pos0 = (ls0 + m0row) >> 1;
    int pos1 = (ls0 + m0row + 8) >> 1;
    int vRow = lane & 15;
    int vColB = (lane >> 4) * 16;

    int ldr = t128 >> 1, ldc = (t128 & 1) * 64;
    {
        int j0 = (0 * 2 + wg) * 64;
        const __nv_bfloat16* ks = kg + (size_t)(b * S_ + j0 + ldr) * HD_ + ldc;
        const __nv_bfloat16* vs = vg + (size_t)(b * S_ + j0 + ldr) * HD_ + ldc;
        uint32_t kd = sKS + ldr * 272 + ldc * 2;
        uint32_t vd = sVS + ldr * 272 + ldc * 2;
        #pragma unroll
        for (int i = 0; i < 8; i++) {
            CPASYNC16(kd + i * 16, ks + i * 8);
            CPASYNC16(vd + i * 16, vs + i * 8);
        }
        CPCOMMIT();
    }

    for (int t = 0; t < 8; t++) {
        if (t + 1 < 8) {
            int j0 = ((t + 1) * 2 + wg) * 64;
            uint32_t boff = ((t + 1) & 1) * ATT_BUFS;
            const __nv_bfloat16* ks = kg + (size_t)(b * S_ + j0 + ldr) * HD_ + ldc;
            const __nv_bfloat16* vs = vg + (size_t)(b * S_ + j0 + ldr) * HD_ + ldc;
            uint32_t kd = sKS + boff + ldr * 272 + ldc * 2;
            uint32_t vd = sVS + boff + ldr * 272 + ldc * 2;
            #pragma unroll
            for (int i = 0; i < 8; i++) {
                CPASYNC16(kd + i * 16, ks + i * 8);
                CPASYNC16(vd + i * 16, vs + i * 8);
            }
            CPCOMMIT();
            CPWAIT1();
        } else {
            CPWAIT0();
        }
        __syncthreads();
        uint32_t kbuf = sKS + (t & 1) * ATT_BUFS;
        uint32_t vbuf = sVS + (t & 1) * ATT_BUFS;
        int j0 = (t * 2 + wg) * 64;

        float c[8][4];
        #pragma unroll
        for (int nt = 0; nt < 8; nt++)
            #pragma unroll
            for (int j = 0; j < 4; j++) c[nt][j] = 0.f;
        #pragma unroll
        for (int ks = 0; ks < 8; ks++) {
            uint32_t bfd[8][2];
            #pragma unroll
            for (int np = 0; np < 4; np++) {
                uint32_t x0, x1, x2, x3;
                ldsm4(x0, x1, x2, x3,
                      kbuf + (np * 16 + bRow) * 272 + bColB + ks * 32);
                bfd[np * 2][0] = x0;     bfd[np * 2][1] = x1;
                bfd[np * 2 + 1][0] = x2; bfd[np * 2 + 1][1] = x3;
            }
            #pragma unroll
            for (int nt = 0; nt < 8; nt++)
                mma16816(c[nt], qf[ks], bfd[nt]);
        }
        #pragma unroll
        for (int nt = 0; nt < 8; nt++) {
            int j = j0 + nt * 8 + cA;
            int i00 = min(max(j - pos0, -64), 64) + 64;
            int i01 = min(max(j + 1 - pos0, -64), 64) + 64;
            int i10 = min(max(j - pos1, -64), 64) + 64;
            int i11 = min(max(j + 1 - pos1, -64), 64) + 64;
            c[nt][0] += Rl[m0row * 132 + i00];
            c[nt][1] += Rl[m0row * 132 + i01];
            c[nt][2] += Rl[(m0row + 8) * 132 + i10];
            c[nt][3] += Rl[(m0row + 8) * 132 + i11];
        }
        float mx0 = -1e30f, mx1 = -1e30f;
        #pragma unroll
        for (int nt = 0; nt < 8; nt++) {
            mx0 = fmaxf(mx0, fmaxf(c[nt][0], c[nt][1]));
            mx1 = fmaxf(mx1, fmaxf(c[nt][2], c[nt][3]));
        }
        mx0 = fmaxf(mx0, __shfl_xor_sync(0xffffffffu, mx0, 1));
        mx0 = fmaxf(mx0, __shfl_xor_sync(0xffffffffu, mx0, 2));
        mx1 = fmaxf(mx1, __shfl_xor_sync(0xffffffffu, mx1, 1));
        mx1 = fmaxf(mx1, __shfl_xor_sync(0xffffffffu, mx1, 2));
        float mn0 = fmaxf(m_run0, mx0), mn1 = fmaxf(m_run1, mx1);
        float sc0 = __expf(m_run0 - mn0), sc1 = __expf(m_run1 - mn1);
        m_run0 = mn0; m_run1 = mn1;
        float rs0 = 0.f, rs1 = 0.f;
        #pragma unroll
        for (int nt = 0; nt < 8; nt++) {
            c[nt][0] = __expf(c[nt][0] - mn0); rs0 += c[nt][0];
            c[nt][1] = __expf(c[nt][1] - mn0); rs0 += c[nt][1];
            c[nt][2] = __expf(c[nt][2] - mn1); rs1 += c[nt][2];
            c[nt][3] = __expf(c[nt][3] - mn1); rs1 += c[nt][3];
        }
        rs0 += __shfl_xor_sync(0xffffffffu, rs0, 1);
        rs0 += __shfl_xor_sync(0xffffffffu, rs0, 2);
        rs1 += __shfl_xor_sync(0xffffffffu, rs1, 1);
        rs1 += __shfl_xor_sync(0xffffffffu, rs1, 2);
        l_run0 = l_run0 * sc0 + rs0;
        l_run1 = l_run1 * sc1 + rs1;
        #pragma unroll
        for (int nt = 0; nt < 16; nt++) {
            ctx[nt][0] *= sc0; ctx[nt][1] *= sc0;
            ctx[nt][2] *= sc1; ctx[nt][3] *= sc1;
        }
        uint32_t pf[4][4];
        #pragma unroll
        for (int k2 = 0; k2 < 4; k2++) {
            pf[k2][0] = packbf(c[2 * k2][0], c[2 * k2][1]);
            pf[k2][1] = packbf(c[2 * k2][2], c[2 * k2][3]);
            pf[k2][2] = packbf(c[2 * k2 + 1][0], c[2 * k2 + 1][1]);
            pf[k2][3] = packbf(c[2 * k2 + 1][2], c[2 * k2 + 1][3]);
        }
        #pragma unroll
        for (int k2 = 0; k2 < 4; k2++) {
            #pragma unroll
            for (int dp = 0; dp < 8; dp++) {
                uint32_t x0, x1, x2, x3;
                ldsm4t(x0, x1, x2, x3,
                       vbuf + (k2 * 16 + vRow) * 272 + dp * 32 + vColB);
                uint32_t b0[2] = {x0, x1};
                uint32_t b1[2] = {x2, x3};
                mma16816(ctx[2 * dp], pf[k2], b0);
                mma16816(ctx[2 * dp + 1], pf[k2], b1);
            }
        }
        __syncthreads();
    }

    if ((lane & 3) == 0) {
        sM[wg * 64 + m0row] = m_run0;     sL[wg * 64 + m0row] = l_run0;
        sM[wg * 64 + m0row + 8] = m_run1; sL[wg * 64 + m0row + 8] = l_run1;
    }
    __syncthreads();
    float mo0 = sM[(1 - wg) * 64 + m0row];
    float mo1 = sM[(1 - wg) * 64 + m0row + 8];
    float lo0 = sL[(1 - wg) * 64 + m0row];
    float lo1 = sL[(1 - wg) * 64 + m0row + 8];
    float M0 = fmaxf(m_run0, mo0), M1 = fmaxf(m_run1, mo1);
    float s0 = __expf(m_run0 - M0), s1 = __expf(m_run1 - M1);
    float lt0 = l_run0 * s0 + lo0 * __expf(mo0 - M0);
    float lt1 = l_run1 * s1 + lo1 * __expf(mo1 - M1);
    #pragma unroll
    for (int nt = 0; nt < 16; nt++) {
        ctx[nt][0] *= s0; ctx[nt][1] *= s0;
        ctx[nt][2] *= s1; ctx[nt][3] *= s1;
    }
    __syncthreads();
    if (wg == 1) {
        #pragma unroll
        for (int nt = 0; nt < 16; nt++) {
            int col = nt * 8 + cA;
            Rl[m0row * 132 + col]           = ctx[nt][0];
            Rl[m0row * 132 + col + 1]       = ctx[nt][1];
            Rl[(m0row + 8) * 132 + col]     = ctx[nt][2];
            Rl[(m0row + 8) * 132 + col + 1] = ctx[nt][3];
        }
    }
    __syncthreads();
    if (wg == 0) {
        float inv0 = 1.f / lt0, inv1 = 1.f / lt1;
        #pragma unroll
        for (int nt = 0; nt < 16; nt++) {
            int col = nt * 8 + cA;
            float v0 = (ctx[nt][0] + Rl[m0row * 132 + col]) * inv0;
            float v1 = (ctx[nt][1] + Rl[m0row * 132 + col + 1]) * inv0;
            float v2 = (ctx[nt][2] + Rl[(m0row + 8) * 132 + col]) * inv1;
            float v3 = (ctx[nt][3] + Rl[(m0row + 8) * 132 + col + 1]) * inv1;
            *(uint32_t*)(ctxg + (size_t)(gs0 + m0row) * HD_ + col) = packbf(v0, v1);
            *(uint32_t*)(ctxg + (size_t)(gs0 + m0row + 8) * HD_ + col) = packbf(v2, v3);
        }
    }
}

// ---------------------------------------------------------------------------
// Host launcher
// ---------------------------------------------------------------------------
extern "C" void kernel_launch(void* const* d_in, const int* in_sizes, int n_in,
                              void* d_out, int out_size) {
    const float* src  = (const float*)d_in[0];
    const float* ln1w = (const float*)d_in[1];
    const float* ln1b = (const float*)d_in[2];
    const float* ln2w = (const float*)d_in[3];
    const float* ln2b = (const float*)d_in[4];
    const float* agw  = (const float*)d_in[5];
    const float* qw   = (const float*)d_in[6];
    const float* qb   = (const float*)d_in[7];
    const float* kw   = (const float*)d_in[8];
    const float* kb   = (const float*)d_in[9];
    const float* vw   = (const float*)d_in[10];
    const float* vb   = (const float*)d_in[11];
    const float* ow   = (const float*)d_in[12];
    const float* ob   = (const float*)d_in[13];
    const float* rel  = (const float*)d_in[14];
    const float* fgw  = (const float*)d_in[15];
    const float* w1   = (const float*)d_in[16];
    const float* b1   = (const float*)d_in[17];
    const float* w2   = (const float*)d_in[18];
    const float* b2   = (const float*)d_in[19];
    float* out = (float*)d_out;

    float *gwa, *gwf, *kvb;
    int *cnta, *cntf, *lista, *listf;
    __nv_bfloat16 *xnbf, *xn2bf, *qbf, *kvbf, *ctxbf, *hbf, *yabf, *wbf;
    cudaGetSymbolAddress((void**)&gwa,   g_gwa);
    cudaGetSymbolAddress((void**)&gwf,   g_gwf);
    cudaGetSymbolAddress((void**)&kvb,   g_kvb);
    cudaGetSymbolAddress((void**)&cnta,  g_cnt_a);
    cudaGetSymbolAddress((void**)&cntf,  g_cnt_f);
    cudaGetSymbolAddress((void**)&lista, g_list_a);
    cudaGetSymbolAddress((void**)&listf, g_list_f);
    cudaGetSymbolAddress((void**)&xnbf,  g_xn_bf);
    cudaGetSymbolAddress((void**)&xn2bf, g_xn2_bf);
    cudaGetSymbolAddress((void**)&qbf,   g_q_bf);
    cudaGetSymbolAddress((void**)&kvbf,  g_kv_bf);
    cudaGetSymbolAddress((void**)&ctxbf, g_ctx_bf);
    cudaGetSymbolAddress((void**)&hbf,   g_h_bf);
    cudaGetSymbolAddress((void**)&yabf,  g_ya_bf);
    cudaGetSymbolAddress((void**)&wbf,   g_wbf);

    __nv_bfloat16* w1t  = wbf + WSEG_W1;
    __nv_bfloat16* w2t  = wbf + WSEG_W2;
    __nv_bfloat16* qwt  = wbf + WSEG_QW;
    __nv_bfloat16* owt  = wbf + WSEG_OW;
    __nv_bfloat16* kvwt = wbf + WSEG_KW;

    static cudaStream_t s1 = nullptr;
    static cudaEvent_t ev_fork = nullptr, ev_join = nullptr;
    static bool attr_set = []() {
        cudaFuncSetAttribute(attn_mma_k,
                             cudaFuncAttributeMaxDynamicSharedMemorySize,
                             ATT2_SMEM);
        cudaFuncSetAttribute(qkv_k,
                             cudaFuncAttributeMaxDynamicSharedMemorySize, GEMM_SMEM_BM64);
        cudaFuncSetAttribute(mmasync_gemm_k<HD_, 64, false, false, true, true, false>,
                             cudaFuncAttributeMaxDynamicSharedMemorySize, GEMM_SMEM_BM64);
        cudaFuncSetAttribute(mmasync_gemm_k<D_, 128, true, true, false, true, false>,
                             cudaFuncAttributeMaxDynamicSharedMemorySize, GEMM_SMEM_BM128);
        cudaFuncSetAttribute(mmasync_gemm_k<FH_, 128, false, false, true, false, true>,
                             cudaFuncAttributeMaxDynamicSharedMemorySize, GEMM_SMEM_BM128);
        return true;
    }();
    (void)attr_set;
    if (!s1) {
        cudaStreamCreateWithFlags(&s1, cudaStreamNonBlocking);
        cudaEventCreateWithFlags(&ev_fork, cudaEventDisableTiming);
        cudaEventCreateWithFlags(&ev_join, cudaEventDisableTiming);
    }

    // fork: weight conversion on side stream, concurrent with setup+ln1
    cudaEventRecord(ev_fork, 0);
    cudaStreamWaitEvent(s1, ev_fork, 0);
    conv_all_k<<<(WSEG_END / 4 + 255) / 256, 256, 0, s1>>>(w1, w2, qw, ow, kw, vw);
    cudaEventRecord(ev_join, s1);

    setup_k<<<(2 * CAP_) / 256, 256>>>(kb, vb);
    ln1_k<<<NTOK_, 256>>>(src, ln1w, ln1b, agw, xnbf);

    cudaStreamWaitEvent(0, ev_join, 0);

    // fused K/V + Q projection
    qkv_k<<<dim3(1, NTOK_ / 64, 2 + EA_), 256, GEMM_SMEM_BM64>>>(
        xnbf, kvwt, qwt, kvb, qb, kvbf, qbf, lista, cnta,
        0.08838834764831845f);

    // flash attention (double-buffered)
    attn_mma_k<<<NTS_ / 64, 256, ATT2_SMEM>>>(
        qbf, kvbf, kvbf + (size_t)NTOK_ * HD_, rel, ctxbf);

    // per-expert output projection, gated (bf16 out), BM=64
    mmasync_gemm_k<HD_, 64, false, false, true, true, false>
        <<<dim3(D_ / 128, CAP_ / 64, EA_), 256, GEMM_SMEM_BM64>>>(
        ctxbf, owt, ob, D_, (void*)yabf, D_, 0,
        lista, cnta, gwa, 1.f);

    // residual + LN2 + FFN router; residual -> out
    combine_ln2_k<<<NTOK_, 256>>>(src, yabf, ln2w, ln2b, fgw, out, xn2bf);

    // FFN, BM=128: w1 (relu -> bf16 h), w2 accumulates into out
    mmasync_gemm_k<D_, 128, true, true, false, true, false>
        <<<dim3(FH_ / 128, CAP_ / 128, EF_), 256, GEMM_SMEM_BM128>>>(
        xn2bf, w1t, b1, FH_, (void*)hbf, FH_, 0,
        listf, cntf, nullptr, 1.f);
    mmasync_gemm_k<FH_, 128, false, false, true, false, true>
        <<<dim3(D_ / 128, CAP_ / 128, EF_), 256, GEMM_SMEM_BM128>>>(
        hbf, w2t, b2, D_, (void*)out, D_, 0,
        listf, cntf, gwf, 1.f);
}

// round 16
// speedup vs baseline: 1.0335x; 1.0335x over previous
#include <cuda_runtime.h>
#include <cuda_bf16.h>
#include <math.h>
#include <stdint.h>

// ---------------------------------------------------------------------------
// Problem constants
// ---------------------------------------------------------------------------
#define D_    1024
#define HD_   128
#define EA_   8
#define EF_   16
#define FH_   512
#define S_    1024
#define B_    4
#define NTOK_ 4096
#define NTS_  8192
#define CAP_  4096

#define WSEG_W1 0
#define WSEG_W2 8388608
#define WSEG_QW 16777216
#define WSEG_OW 17825792
#define WSEG_KW 18874368
#define WSEG_VW 19005440
#define WSEG_END 19136512

// ---------------------------------------------------------------------------
// PTX helpers
// ---------------------------------------------------------------------------
__device__ __forceinline__ uint32_t smem_to_u32(const void* p) {
    uint32_t a;
    asm("{ .reg .u64 t; cvta.to.shared.u64 t, %1; cvt.u32.u64 %0, t; }"
        : "=r"(a) : "l"(p));
    return a;
}
__device__ __forceinline__ void ldsm4(uint32_t& r0, uint32_t& r1,
                                      uint32_t& r2, uint32_t& r3, uint32_t a) {
    asm volatile("ldmatrix.sync.aligned.m8n8.x4.shared.b16 {%0,%1,%2,%3}, [%4];"
                 : "=r"(r0), "=r"(r1), "=r"(r2), "=r"(r3) : "r"(a));
}
__device__ __forceinline__ void ldsm4t(uint32_t& r0, uint32_t& r1,
                                       uint32_t& r2, uint32_t& r3, uint32_t a) {
    asm volatile("ldmatrix.sync.aligned.m8n8.x4.trans.shared.b16 {%0,%1,%2,%3}, [%4];"
                 : "=r"(r0), "=r"(r1), "=r"(r2), "=r"(r3) : "r"(a));
}
__device__ __forceinline__ void mma16816(float* c, const uint32_t* a,
                                         const uint32_t* b) {
    asm volatile(
        "mma.sync.aligned.m16n8k16.row.col.f32.bf16.bf16.f32 "
        "{%0,%1,%2,%3}, {%4,%5,%6,%7}, {%8,%9}, {%0,%1,%2,%3};"
        : "+f"(c[0]), "+f"(c[1]), "+f"(c[2]), "+f"(c[3])
        : "r"(a[0]), "r"(a[1]), "r"(a[2]), "r"(a[3]), "r"(b[0]), "r"(b[1]));
}
__device__ __forceinline__ uint32_t packbf(float a, float b) {
    __nv_bfloat162 p = __floats2bfloat162_rn(a, b);
    return *(uint32_t*)&p;
}
__device__ __forceinline__ void redv2(float* p, float v0, float v1) {
    asm volatile("red.global.add.v2.f32 [%0], {%1, %2};"
                 :: "l"(p), "f"(v0), "f"(v1) : "memory");
}
#define CPASYNC16(dst, src) \
    asm volatile("cp.async.cg.shared.global [%0], [%1], 16;" \
                 :: "r"(dst), "l"(src))
#define CPCOMMIT() asm volatile("cp.async.commit_group;" ::: "memory")
#define CPWAIT1()  asm volatile("cp.async.wait_group 1;" ::: "memory")
#define CPWAIT0()  asm volatile("cp.async.wait_group 0;" ::: "memory")

// ---------------------------------------------------------------------------
// Device-global scratch
// ---------------------------------------------------------------------------
__device__ float g_gwa [NTS_];
__device__ float g_gwf [NTS_];
__device__ int   g_cnt_a [EA_];
__device__ int   g_cnt_f [EF_];
__device__ int   g_list_a[EA_ * CAP_];
__device__ int   g_list_f[EF_ * CAP_];
__device__ int   g_list_id[CAP_];
__device__ float g_kvb [2 * HD_];
__device__ __nv_bfloat16 g_xn_bf [NTOK_ * D_];
__device__ __nv_bfloat16 g_xn2_bf[NTOK_ * D_];
__device__ __nv_bfloat16 g_q_bf  [NTS_  * HD_];
__device__ __nv_bfloat16 g_kv_bf [2 * NTOK_ * HD_];
__device__ __nv_bfloat16 g_ctx_bf[NTS_  * HD_];
__device__ __nv_bfloat16 g_h_bf  [NTS_  * FH_];
__device__ __nv_bfloat16 g_ya_bf [NTS_  * D_];
__device__ __nv_bfloat16 g_wbf [WSEG_END];

// ---------------------------------------------------------------------------
// Setup
// ---------------------------------------------------------------------------
__global__ void __launch_bounds__(256) setup_k(const float* __restrict__ kb,
                                               const float* __restrict__ vb) {
    int i = blockIdx.x * 256 + threadIdx.x;
    if (i < EA_) g_cnt_a[i] = 0;
    if (i < EF_) g_cnt_f[i] = 0;
    if (i < CAP_) g_list_id[i] = i;
    if (i < HD_) g_kvb[i] = kb[i];
    else if (i >= CAP_ && i < CAP_ + HD_) g_kvb[HD_ + i - CAP_] = vb[i - CAP_];
}

// ---------------------------------------------------------------------------
// Flat fp32->bf16 weight convert
// ---------------------------------------------------------------------------
__global__ void __launch_bounds__(256) conv_all_k(
    const float* __restrict__ w1, const float* __restrict__ w2,
    const float* __restrict__ qw, const float* __restrict__ ow,
    const float* __restrict__ kw, const float* __restrict__ vw)
{
    size_t el = ((size_t)blockIdx.x * 256 + threadIdx.x) * 4;
    if (el >= WSEG_END) return;
    const float* src;
    if (el < WSEG_W2)      src = w1 + (el - WSEG_W1);
    else if (el < WSEG_QW) src = w2 + (el - WSEG_W2);
    else if (el < WSEG_OW) src = qw + (el - WSEG_QW);
    else if (el < WSEG_KW) src = ow + (el - WSEG_OW);
    else if (el < WSEG_VW) src = kw + (el - WSEG_KW);
    else                   src = vw + (el - WSEG_VW);
    float4 v = *(const float4*)src;
    uint2 st;
    st.x = packbf(v.x, v.y); st.y = packbf(v.z, v.w);
    *(uint2*)(g_wbf + el) = st;
}

// ---------------------------------------------------------------------------
// LayerNorm 1 + attention router fused
// ---------------------------------------------------------------------------
__global__ void __launch_bounds__(256) ln1_k(
    const float* __restrict__ x, const float* __restrict__ w,
    const float* __restrict__ b, const float* __restrict__ gwm,
    __nv_bfloat16* __restrict__ ybf)
{
    int t = blockIdx.x, tid = threadIdx.x;
    int lane = tid & 31, wrp = tid >> 5;
    float4 v = ((const float4*)(x + (size_t)t * D_))[tid];
    float s = v.x + v.y + v.z + v.w;
    float q = fmaf(v.x, v.x, fmaf(v.y, v.y, fmaf(v.z, v.z, v.w * v.w)));
    __shared__ float ss[8], sq[8];
    __shared__ float sp[8][EA_];
    #pragma unroll
    for (int o = 16; o; o >>= 1) {
        s += __shfl_xor_sync(0xffffffffu, s, o);
        q += __shfl_xor_sync(0xffffffffu, q, o);
    }
    if (lane == 0) { ss[wrp] = s; sq[wrp] = q; }
    __syncthreads();
    if (tid == 0) {
        float a = 0.f, c = 0.f;
        #pragma unroll
        for (int i = 0; i < 8; i++) { a += ss[i]; c += sq[i]; }
        ss[0] = a; sq[0] = c;
    }
    __syncthreads();
    float mu  = ss[0] * (1.f / D_);
    float var = sq[0] * (1.f / D_) - mu * mu;
    float rs  = rsqrtf(var + 1e-5f);
    float4 wv = ((const float4*)w)[tid];
    float4 bv = ((const float4*)b)[tid];
    float o0 = (v.x - mu) * rs * wv.x + bv.x;
    float o1 = (v.y - mu) * rs * wv.y + bv.y;
    float o2 = (v.z - mu) * rs * wv.z + bv.z;
    float o3 = (v.w - mu) * rs * wv.w + bv.w;
    uint2 st;
    st.x = packbf(o0, o1); st.y = packbf(o2, o3);
    *(uint2*)(ybf + (size_t)t * D_ + tid * 4) = st;

    float p[EA_];
    #pragma unroll
    for (int e = 0; e < EA_; e++) p[e] = 0.f;
    float xs[4] = {o0, o1, o2, o3};
    const float4* g4 = (const float4*)(gwm + (size_t)(tid * 4) * EA_);
    #pragma unroll
    for (int j = 0; j < 4; j++) {
        float4 ga = g4[j * 2], gb = g4[j * 2 + 1];
        p[0] = fmaf(xs[j], ga.x, p[0]); p[1] = fmaf(xs[j], ga.y, p[1]);
        p[2] = fmaf(xs[j], ga.z, p[2]); p[3] = fmaf(xs[j], ga.w, p[3]);
        p[4] = fmaf(xs[j], gb.x, p[4]); p[5] = fmaf(xs[j], gb.y, p[5]);
        p[6] = fmaf(xs[j], gb.z, p[6]); p[7] = fmaf(xs[j], gb.w, p[7]);
    }
    #pragma unroll
    for (int e = 0; e < EA_; e++)
        #pragma unroll
        for (int o = 16; o; o >>= 1)
            p[e] += __shfl_xor_sync(0xffffffffu, p[e], o);
    if (lane == 0)
        #pragma unroll
        for (int e = 0; e < EA_; e++) sp[wrp][e] = p[e];
    __syncthreads();
    if (tid == 0) {
        float l[EA_];
        #pragma unroll
        for (int e = 0; e < EA_; e++) {
            float a = 0.f;
            #pragma unroll
            for (int wdx = 0; wdx < 8; wdx++) a += sp[wdx][e];
            l[e] = a;
        }
        int i0 = 0; float v0 = l[0];
        #pragma unroll
        for (int e = 1; e < EA_; e++) if (l[e] > v0) { v0 = l[e]; i0 = e; }
        int i1 = -1; float v1 = -1e30f;
        #pragma unroll
        for (int e = 0; e < EA_; e++)
            if (e != i0 && l[e] > v1) { v1 = l[e]; i1 = e; }
        float e1 = __expf(v1 - v0);
        float inv = 1.f / (1.f + e1);
        g_gwa[2 * t]     = inv;
        g_gwa[2 * t + 1] = e1 * inv;
        int p0 = atomicAdd(&g_cnt_a[i0], 1);
        g_list_a[i0 * CAP_ + p0] = 2 * t;
        int p1 = atomicAdd(&g_cnt_a[i1], 1);
        g_list_a[i1 * CAP_ + p1] = 2 * t + 1;
    }
}

// ---------------------------------------------------------------------------
// Residual-add (ya bf16) + LayerNorm 2 + FFN router fused; residual -> out
// ---------------------------------------------------------------------------
__global__ void __launch_bounds__(256) combine_ln2_k(
    const float* __restrict__ src, const __nv_bfloat16* __restrict__ ya,
    const float* __restrict__ w, const float* __restrict__ b,
    const float* __restrict__ gwm,
    float* __restrict__ out, __nv_bfloat16* __restrict__ xn2bf)
{
    int t = blockIdx.x, tid = threadIdx.x;
    int lane = tid & 31, wrp = tid >> 5;
    float4 v  = ((const float4*)(src + (size_t)t * D_))[tid];
    uint2 u0 = *(const uint2*)(ya + (size_t)(2 * t) * D_ + tid * 4);
    uint2 u1 = *(const uint2*)(ya + (size_t)(2 * t + 1) * D_ + tid * 4);
    {
        __nv_bfloat162 a0 = *(__nv_bfloat162*)&u0.x;
        __nv_bfloat162 a1 = *(__nv_bfloat162*)&u0.y;
        __nv_bfloat162 b0 = *(__nv_bfloat162*)&u1.x;
        __nv_bfloat162 b1 = *(__nv_bfloat162*)&u1.y;
        v.x += __bfloat162float(a0.x) + __bfloat162float(b0.x);
        v.y += __bfloat162float(a0.y) + __bfloat162float(b0.y);
        v.z += __bfloat162float(a1.x) + __bfloat162float(b1.x);
        v.w += __bfloat162float(a1.y) + __bfloat162float(b1.y);
    }
    ((float4*)(out + (size_t)t * D_))[tid] = v;

    float s = v.x + v.y + v.z + v.w;
    float q = fmaf(v.x, v.x, fmaf(v.y, v.y, fmaf(v.z, v.z, v.w * v.w)));
    __shared__ float ss[8], sq[8];
    __shared__ float sp[8][EF_];
    #pragma unroll
    for (int o = 16; o; o >>= 1) {
        s += __shfl_xor_sync(0xffffffffu, s, o);
        q += __shfl_xor_sync(0xffffffffu, q, o);
    }
    if (lane == 0) { ss[wrp] = s; sq[wrp] = q; }
    __syncthreads();
    if (tid == 0) {
        float a = 0.f, c = 0.f;
        #pragma unroll
        for (int i = 0; i < 8; i++) { a += ss[i]; c += sq[i]; }
        ss[0] = a; sq[0] = c;
    }
    __syncthreads();
    float mu  = ss[0] * (1.f / D_);
    float var = sq[0] * (1.f / D_) - mu * mu;
    float rs  = rsqrtf(var + 1e-5f);
    float4 wv = ((const float4*)w)[tid];
    float4 bv = ((const float4*)b)[tid];
    float o0 = (v.x - mu) * rs * wv.x + bv.x;
    float o1 = (v.y - mu) * rs * wv.y + bv.y;
    float o2 = (v.z - mu) * rs * wv.z + bv.z;
    float o3 = (v.w - mu) * rs * wv.w + bv.w;
    uint2 st;
    st.x = packbf(o0, o1); st.y = packbf(o2, o3);
    *(uint2*)(xn2bf + (size_t)t * D_ + tid * 4) = st;

    float p[EF_];
    #pragma unroll
    for (int e = 0; e < EF_; e++) p[e] = 0.f;
    float xs[4] = {o0, o1, o2, o3};
    const float4* g4 = (const float4*)(gwm + (size_t)(tid * 4) * EF_);
    #pragma unroll
    for (int j = 0; j < 4; j++) {
        #pragma unroll
        for (int g = 0; g < 4; g++) {
            float4 gv = g4[j * 4 + g];
            p[g*4+0] = fmaf(xs[j], gv.x, p[g*4+0]);
            p[g*4+1] = fmaf(xs[j], gv.y, p[g*4+1]);
            p[g*4+2] = fmaf(xs[j], gv.z, p[g*4+2]);
            p[g*4+3] = fmaf(xs[j], gv.w, p[g*4+3]);
        }
    }
    #pragma unroll
    for (int e = 0; e < EF_; e++)
        #pragma unroll
        for (int o = 16; o; o >>= 1)
            p[e] += __shfl_xor_sync(0xffffffffu, p[e], o);
    if (lane == 0)
        #pragma unroll
        for (int e = 0; e < EF_; e++) sp[wrp][e] = p[e];
    __syncthreads();
    if (tid == 0) {
        float l[EF_];
        #pragma unroll
        for (int e = 0; e < EF_; e++) {
            float a = 0.f;
            #pragma unroll
            for (int wdx = 0; wdx < 8; wdx++) a += sp[wdx][e];
            l[e] = a;
        }
        int i0 = 0; float v0 = l[0];
        #pragma unroll
        for (int e = 1; e < EF_; e++) if (l[e] > v0) { v0 = l[e]; i0 = e; }
        int i1 = -1; float v1 = -1e30f;
        #pragma unroll
        for (int e = 0; e < EF_; e++)
            if (e != i0 && l[e] > v1) { v1 = l[e]; i1 = e; }
        float e1 = __expf(v1 - v0);
        float inv = 1.f / (1.f + e1);
        g_gwf[2 * t]     = inv;
        g_gwf[2 * t + 1] = e1 * inv;
        int p0 = atomicAdd(&g_cnt_f[i0], 1);
        g_list_f[i0 * CAP_ + p0] = 2 * t;
        int p1 = atomicAdd(&g_cnt_f[i1], 1);
        g_list_f[i1 * CAP_ + p1] = 2 * t + 1;
    }
}

// ---------------------------------------------------------------------------
// Generic grouped GEMM, 3-stage cp.async ring, ONE barrier per stage.
// ---------------------------------------------------------------------------
#define LDAB 72
#define LDB_ 136

template<int KTOT, int BM, bool TOKROW, bool RELU, bool GATE, bool OUTBF, bool ACCUM>
__global__ void __launch_bounds__(256) mmasync_gemm_k(
    const __nv_bfloat16* __restrict__ Abase,
    const __nv_bfloat16* __restrict__ Bbase,
    const float* __restrict__ biasb, int Nfull,
    void* __restrict__ Yv, int ldy, size_t eStrideY,
    const int* __restrict__ lists, const int* __restrict__ cnts,
    const float* __restrict__ gw, float scale)
{
    constexpr int MWARPS = BM / 32;
    constexpr int NWARPS = 8 / MWARPS;
    constexpr int WN     = 128 / NWARPS;
    constexpr int NT     = WN / 8;
    constexpr int A_CH   = BM * 8 / 256;
    constexpr int ASTG   = BM * LDAB * 2;
    constexpr int STAGE  = ASTG + 64 * LDB_ * 2;

    int e = blockIdx.z;
    int cnt = cnts[e];
    int row0 = blockIdx.y * BM;
    if (row0 >= cnt) return;
    int n0 = blockIdx.x * 128;
    const int* list = lists + e * CAP_;

    extern __shared__ char dynsm[];
    __shared__ float bias_s[128];
    __shared__ float gate_s[BM];
    __shared__ int   slot_s[BM];

    int tid = threadIdx.x;
    int wid = tid >> 5, lane = tid & 31;

    if (tid < 128) bias_s[tid] = biasb[(size_t)e * Nfull + n0 + tid];
    if (tid < BM) {
        int r = min(row0 + tid, cnt - 1);
        int sl = list[r];
        slot_s[tid] = sl;
        gate_s[tid] = GATE ? gw[sl] : 1.f;
    }

    uint32_t sBase = smem_to_u32(dynsm);
    uint32_t sA0 = sBase;
    uint32_t sB0 = sBase + ASTG;

    const __nv_bfloat16* Bexp = Bbase + (size_t)e * Nfull * KTOT;
    const __nv_bfloat16* aSrc[A_CH];
    uint32_t aDst[A_CH];
    #pragma unroll
    for (int i = 0; i < A_CH; i++) {
        int idx = tid + i * 256;
        int am = idx >> 3, ac = idx & 7;
        int r = min(row0 + am, cnt - 1);
        int sl = list[r];
        int gr = TOKROW ? (sl >> 1) : sl;
        aSrc[i] = Abase + (size_t)gr * KTOT + ac * 8;
        aDst[i] = sA0 + (am * LDAB + ac * 8) * 2;
    }
    const __nv_bfloat16* bSrc[4];
    uint32_t bDst[4];
    #pragma unroll
    for (int i = 0; i < 4; i++) {
        int idx = tid + i * 256;
        int bk = idx >> 4, bn = (idx & 15) * 8;
        bSrc[i] = Bexp + (size_t)bk * Nfull + n0 + bn;
        bDst[i] = sB0 + (bk * LDB_ + bn) * 2;
    }

    int warpM = (wid % MWARPS) * 32;
    int warpN = (wid / MWARPS) * WN;
    uint32_t aAddr = sA0 + ((warpM + (lane & 15)) * LDAB + (lane >> 4) * 8) * 2;
    uint32_t bAddrBase = sB0 + ((lane & 15) * LDB_ + warpN + (lane >> 4) * 8) * 2;

    float acc[2][NT][4];
    #pragma unroll
    for (int mt = 0; mt < 2; mt++)
        #pragma unroll
        for (int nt = 0; nt < NT; nt++)
            #pragma unroll
            for (int j = 0; j < 4; j++) acc[mt][nt][j] = 0.f;

    const int NSTAGE = KTOT / 64;

    // prologue: stages 0 and 1
    #pragma unroll
    for (int i = 0; i < A_CH; i++) CPASYNC16(aDst[i], aSrc[i]);
    #pragma unroll
    for (int i = 0; i < 4; i++) CPASYNC16(bDst[i], bSrc[i]);
    CPCOMMIT();
    if (NSTAGE > 1) {
        #pragma unroll
        for (int i = 0; i < A_CH; i++) CPASYNC16(aDst[i] + STAGE, aSrc[i] + 64);
        #pragma unroll
        for (int i = 0; i < 4; i++)
            CPASYNC16(bDst[i] + STAGE, bSrc[i] + (size_t)64 * Nfull);
        CPCOMMIT();
    }

    for (int st = 0; st < NSTAGE; st++) {
        if (st + 1 < NSTAGE) CPWAIT1(); else CPWAIT0();
        __syncthreads();
        uint32_t off = (st % 3) * STAGE;
        #pragma unroll
        for (int kk = 0; kk < 4; kk++) {
            uint32_t a[2][4];
            ldsm4(a[0][0], a[0][1], a[0][2], a[0][3], aAddr + off + kk * 32);
            ldsm4(a[1][0], a[1][1], a[1][2], a[1][3],
                  aAddr + off + 16 * LDAB * 2 + kk * 32);
            uint32_t b[NT][2];
            #pragma unroll
            for (int np = 0; np < NT / 2; np++) {
                uint32_t r0, r1, r2, r3;
                ldsm4t(r0, r1, r2, r3,
                       bAddrBase + off + kk * (16 * LDB_ * 2) + np * 32);
                b[np * 2][0] = r0;     b[np * 2][1] = r1;
                b[np * 2 + 1][0] = r2; b[np * 2 + 1][1] = r3;
            }
            #pragma unroll
            for (int mt = 0; mt < 2; mt++)
                #pragma unroll
                for (int nt = 0; nt < NT; nt++)
                    mma16816(acc[mt][nt], a[mt], b[nt]);
        }
        // prefetch st+2 AFTER compute: buffer (st+2)%3 disjoint from st%3 and
        // (st+1)%3; the single barrier bounds cross-warp skew to one stage.
        if (st + 2 < NSTAGE) {
            uint32_t boff = ((st + 2) % 3) * STAGE;
            int k0 = (st + 2) * 64;
            #pragma unroll
            for (int i = 0; i < A_CH; i++) CPASYNC16(aDst[i] + boff, aSrc[i] + k0);
            #pragma unroll
            for (int i = 0; i < 4; i++)
                CPASYNC16(bDst[i] + boff, bSrc[i] + (size_t)k0 * Nfull);
            CPCOMMIT();
        }
    }

    int lane4 = lane >> 2;
    int lcol  = (lane & 3) * 2;
    #pragma unroll
    for (int mt = 0; mt < 2; mt++) {
        #pragma unroll
        for (int h = 0; h < 2; h++) {
            int m = warpM + mt * 16 + lane4 + h * 8;
            if (row0 + m >= cnt) continue;
            int sl = slot_s[m];
            float f = gate_s[m];
            int orow = ACCUM ? (sl >> 1) : sl;
            size_t ybase = (size_t)e * eStrideY + (size_t)orow * ldy + n0;
            #pragma unroll
            for (int nt = 0; nt < NT; nt++) {
                int col = warpN + nt * 8 + lcol;
                float v0 = (acc[mt][nt][h * 2 + 0] + bias_s[col]) * scale;
                float v1 = (acc[mt][nt][h * 2 + 1] + bias_s[col + 1]) * scale;
                if (RELU) { v0 = fmaxf(v0, 0.f); v1 = fmaxf(v1, 0.f); }
                v0 *= f; v1 *= f;
                if (ACCUM) {
                    redv2((float*)Yv + ybase + col, v0, v1);
                } else if (OUTBF) {
                    *(uint32_t*)((__nv_bfloat16*)Yv + ybase + col) = packbf(v0, v1);
                } else {
                    float2 p = make_float2(v0, v1);
                    *(float2*)((float*)Yv + ybase + col) = p;
                }
            }
        }
    }
}

#define GEMM_SMEM_BM64  (3 * (64 * LDAB * 2 + 64 * LDB_ * 2))
#define GEMM_SMEM_BM128 (3 * (128 * LDAB * 2 + 64 * LDB_ * 2))

// ---------------------------------------------------------------------------
// Fused K/V + Q projection — 3-stage ring, ONE barrier per stage
// ---------------------------------------------------------------------------
__global__ void __launch_bounds__(256) qkv_k(
    const __nv_bfloat16* __restrict__ Abase,
    const __nv_bfloat16* __restrict__ kvw,
    const __nv_bfloat16* __restrict__ qwv,
    const float* __restrict__ kvb2,
    const float* __restrict__ qb,
    __nv_bfloat16* __restrict__ kvout,
    __nv_bfloat16* __restrict__ qout,
    const int* __restrict__ lista,
    const int* __restrict__ cnta,
    float qscale)
{
    constexpr int BM = 64, NT = 4;
    constexpr int ASTG  = BM * LDAB * 2;
    constexpr int STAGE = ASTG + 64 * LDB_ * 2;
    const int KTOT = D_, NSTAGE = D_ / 64;

    int z = blockIdx.z;
    bool isQ = (z >= 2);
    int e = isQ ? (z - 2) : z;
    int cnt = isQ ? cnta[e] : NTOK_;
    int row0 = blockIdx.y * BM;
    if (row0 >= cnt) return;
    const int* list = isQ ? (lista + e * CAP_) : g_list_id;
    const __nv_bfloat16* Bexp = (isQ ? qwv : kvw) + (size_t)e * HD_ * D_;
    const float* bias = (isQ ? qb : kvb2) + (size_t)e * HD_;
    float scale = isQ ? qscale : 1.f;
    __nv_bfloat16* Yp = isQ ? qout : (kvout + (size_t)e * NTOK_ * HD_);

    extern __shared__ char dynsm[];
    __shared__ float bias_s[128];
    __shared__ int   slot_s[BM];

    int tid = threadIdx.x;
    int wid = tid >> 5, lane = tid & 31;

    if (tid < 128) bias_s[tid] = bias[tid];
    if (tid < BM) {
        int r = min(row0 + tid, cnt - 1);
        slot_s[tid] = list[r];
    }

    uint32_t sBase = smem_to_u32(dynsm);
    uint32_t sA0 = sBase;
    uint32_t sB0 = sBase + ASTG;

    const __nv_bfloat16* aSrc[2];
    uint32_t aDst[2];
    #pragma unroll
    for (int i = 0; i < 2; i++) {
        int idx = tid + i * 256;
        int am = idx >> 3, ac = idx & 7;
        int r = min(row0 + am, cnt - 1);
        int sl = list[r];
        int gr = isQ ? (sl >> 1) : sl;
        aSrc[i] = Abase + (size_t)gr * KTOT + ac * 8;
        aDst[i] = sA0 + (am * LDAB + ac * 8) * 2;
    }
    const __nv_bfloat16* bSrc[4];
    uint32_t bDst[4];
    #pragma unroll
    for (int i = 0; i < 4; i++) {
        int idx = tid + i * 256;
        int bk = idx >> 4, bn = (idx & 15) * 8;
        bSrc[i] = Bexp + (size_t)bk * HD_ + bn;
        bDst[i] = sB0 + (bk * LDB_ + bn) * 2;
    }

    int warpM = (wid & 1) * 32;
    int warpN = (wid >> 1) * 32;
    uint32_t aAddr = sA0 + ((warpM + (lane & 15)) * LDAB + (lane >> 4) * 8) * 2;
    uint32_t bAddrBase = sB0 + ((lane & 15) * LDB_ + warpN + (lane >> 4) * 8) * 2;

    float acc[2][NT][4];
    #pragma unroll
    for (int mt = 0; mt < 2; mt++)
        #pragma unroll
        for (int nt = 0; nt < NT; nt++)
            #pragma unroll
            for (int j = 0; j < 4; j++) acc[mt][nt][j] = 0.f;

    #pragma unroll
    for (int i = 0; i < 2; i++) CPASYNC16(aDst[i], aSrc[i]);
    #pragma unroll
    for (int i = 0; i < 4; i++) CPASYNC16(bDst[i], bSrc[i]);
    CPCOMMIT();
    #pragma unroll
    for (int i = 0; i < 2; i++) CPASYNC16(aDst[i] + STAGE, aSrc[i] + 64);
    #pragma unroll
    for (int i = 0; i < 4; i++)
        CPASYNC16(bDst[i] + STAGE, bSrc[i] + (size_t)64 * HD_);
    CPCOMMIT();

    for (int st = 0; st < NSTAGE; st++) {
        if (st + 1 < NSTAGE) CPWAIT1(); else CPWAIT0();
        __syncthreads();
        uint32_t off = (st % 3) * STAGE;
        #pragma unroll
        for (int kk = 0; kk < 4; kk++) {
            uint32_t a[2][4];
            ldsm4(a[0][0], a[0][1], a[0][2], a[0][3], aAddr + off + kk * 32);
            ldsm4(a[1][0], a[1][1], a[1][2], a[1][3],
                  aAddr + off + 16 * LDAB * 2 + kk * 32);
            uint32_t b[NT][2];
            #pragma unroll
            for (int np = 0; np < NT / 2; np++) {
                uint32_t r0, r1, r2, r3;
                ldsm4t(r0, r1, r2, r3,
                       bAddrBase + off + kk * (16 * LDB_ * 2) + np * 32);
                b[np * 2][0] = r0;     b[np * 2][1] = r1;
                b[np * 2 + 1][0] = r2; b[np * 2 + 1][1] = r3;
            }
            #pragma unroll
            for (int mt = 0; mt < 2; mt++)
                #pragma unroll
                for (int nt = 0; nt < NT; nt++)
                    mma16816(acc[mt][nt], a[mt], b[nt]);
        }
        if (st + 2 < NSTAGE) {
            uint32_t boff = ((st + 2) % 3) * STAGE;
            int k0 = (st + 2) * 64;
            #pragma unroll
            for (int i = 0; i < 2; i++) CPASYNC16(aDst[i] + boff, aSrc[i] + k0);
            #pragma unroll
            for (int i = 0; i < 4; i++)
                CPASYNC16(bDst[i] + boff, bSrc[i] + (size_t)k0 * HD_);
            CPCOMMIT();
        }
    }

    int lane4 = lane >> 2;
    int lcol  = (lane & 3) * 2;
    #pragma unroll
    for (int mt = 0; mt < 2; mt++) {
        #pragma unroll
        for (int h = 0; h < 2; h++) {
            int m = warpM + mt * 16 + lane4 + h * 8;
            if (row0 + m >= cnt) continue;
            int sl = slot_s[m];
            #pragma unroll
            for (int nt = 0; nt < NT; nt++) {
                int col = warpN + nt * 8 + lcol;
                float v0 = (acc[mt][nt][h * 2 + 0] + bias_s[col]) * scale;
                float v1 = (acc[mt][nt][h * 2 + 1] + bias_s[col + 1]) * scale;
                *(uint32_t*)(Yp + (size_t)sl * HD_ + col) = packbf(v0, v1);
            }
        }
    }
}

// ---------------------------------------------------------------------------
// Tensor-core flash attention — K/V cp.async double-buffered
// ---------------------------------------------------------------------------
#define ATT2_QS   0
#define ATT2_KS   17408
#define ATT2_VS   87040
#define ATT2_RL   156672
#define ATT2_SM   190464
#define ATT2_SL   190976
#define ATT2_SMEM 191488
#define ATT_WGS   34816
#define ATT_BUFS  17408

__global__ void __launch_bounds__(256) attn_mma_k(
    const __nv_bfloat16* __restrict__ qg,
    const __nv_bfloat16* __restrict__ kg,
    const __nv_bfloat16* __restrict__ vg,
    const float* __restrict__ rel,
    __nv_bfloat16* __restrict__ ctxg)
{
    extern __shared__ char smraw[];
    __nv_bfloat16* Qs = (__nv_bfloat16*)(smraw + ATT2_QS);
    float* Rl = (float*)(smraw + ATT2_RL);
    float* sM = (float*)(smraw + ATT2_SM);
    float* sL = (float*)(smraw + ATT2_SL);

    int tid = threadIdx.x;
    int wid = tid >> 5, lane = tid & 31;
    int wg = wid >> 2, ww = wid & 3;
    int t128 = tid & 127;

    int gs0 = blockIdx.x * 64;
    int b   = gs0 >> 11;
    int ls0 = gs0 & 2047;

    {
        int r = tid >> 2, cb = (tid & 3) * 32;
        const uint4* src = (const uint4*)(qg + (size_t)(gs0 + r) * HD_ + cb);
        uint4* dst = (uint4*)(smraw + ATT2_QS + r * 272 + cb * 2);
        #pragma unroll
        for (int i = 0; i < 4; i++) dst[i] = src[i];
    }
    {
        int r = t128 >> 1, cb = (t128 & 1) * 64;
        int rr = wg * 64 + r;
        const float* src = rel + (size_t)rr * HD_ + cb;
        char* dst = smraw + ATT2_KS + wg * ATT_WGS + r * 272 + cb * 2;
        #pragma unroll
        for (int i = 0; i < 8; i++) {
            float4 f0 = *(const float4*)(src + i * 8);
            float4 f1 = *(const float4*)(src + i * 8 + 4);
            uint4 st;
            st.x = packbf(f0.x, f0.y); st.y = packbf(f0.z, f0.w);
            st.z = packbf(f1.x, f1.y); st.w = packbf(f1.z, f1.w);
            *(uint4*)(dst + i * 16) = st;
        }
    }
    __syncthreads();

    uint32_t sQ = smem_to_u32(smraw + ATT2_QS);
    uint32_t aQAddr = sQ + (ww * 16 + (lane & 15)) * 272 + (lane >> 4) * 16;
    uint32_t qf[8][4];
    #pragma unroll
    for (int ks = 0; ks < 8; ks++)
        ldsm4(qf[ks][0], qf[ks][1], qf[ks][2], qf[ks][3], aQAddr + ks * 32);

    int bRow = ((lane >> 4) & 1) * 8 + (lane & 7);
    int bColB = ((lane >> 3) & 1) * 16;
    uint32_t sKS = smem_to_u32(smraw + ATT2_KS) + wg * ATT_WGS;
    uint32_t sVS = smem_to_u32(smraw + ATT2_VS) + wg * ATT_WGS;

    int r0 = lane >> 2, cA = (lane & 3) * 2;
    int m0row = ww * 16 + r0;

    {
        float c[8][4];
        #pragma unroll
        for (int nt = 0; nt < 8; nt++)
            #pragma unroll
            for (int j = 0; j < 4; j++) c[nt][j] = 0.f;
        #pragma unroll
        for (int ks = 0; ks < 8; ks++) {
            uint32_t bfd[8][2];
            #pragma unroll
            for (int np = 0; np < 4; np++) {
                uint32_t x0, x1, x2, x3;
                ldsm4(x0, x1, x2, x3,
                      sKS + (np * 16 + bRow) * 272 + bColB + ks * 32);
                bfd[np * 2][0] = x0;     bfd[np * 2][1] = x1;
                bfd[np * 2 + 1][0] = x2; bfd[np * 2 + 1][1] = x3;
            }
            #pragma unroll
            for (int nt = 0; nt < 8; nt++)
                mma16816(c[nt], qf[ks], bfd[nt]);
        }
        #pragma unroll
        for (int nt = 0; nt < 8; nt++) {
            int col = wg * 64 + nt * 8 + cA;
            Rl[m0row * 132 + col]           = c[nt][0];
            Rl[m0row * 132 + col + 1]       = c[nt][1];
            Rl[(m0row + 8) * 132 + col]     = c[nt][2];
            Rl[(m0row + 8) * 132 + col + 1] = c[nt][3];
        }
    }
    {
        int m = tid >> 2, l4 = tid & 3;
        const float* rrow = rel + (size_t)128 * HD_ + l4 * 32;
        const __nv_bfloat16* qrow = Qs + m * 136 + l4 * 32;
        float s = 0.f;
        #pragma unroll
        for (int i = 0; i < 32; i++)
            s = fmaf(__bfloat162float(qrow[i]), rrow[i], s);
        s += __shfl_xor_sync(0xffffffffu, s, 1);
        s += __shfl_xor_sync(0xffffffffu, s, 2);
        if (l4 == 0) Rl[m * 132 + 128] = s;
    }
    __syncthreads();

    float m_run0 = -1e30f, m_run1 = -1e30f;
    float l_run0 = 0.f, l_run1 = 0.f;
    float ctx[16][4];
    #pragma unroll
    for (int nt = 0; nt < 16; nt++)
        #pragma unroll
        for (int j = 0; j < 4; j++) ctx[nt][j] = 0.f;

    int pos0 = (ls0 + m0row) >> 1;
    int pos1 = (ls0 + m0row + 8) >> 1;
    int vRow = lane & 15;
    int vColB = (lane >> 4) * 16;

    int ldr = t128 >> 1, ldc = (t128 & 1) * 64;
    {
        int j0 = (0 * 2 + wg) * 64;
        const __nv_bfloat16* ks = kg + (size_t)(b * S_ + j0 + ldr) * HD_ + ldc;
        const __nv_bfloat16* vs = vg + (size_t)(b * S_ + j0 + ldr) * HD_ + ldc;
        uint32_t kd = sKS + ldr * 272 + ldc * 2;
        uint32_t vd = sVS + ldr * 272 + ldc * 2;
        #pragma unroll
        for (int i = 0; i < 8; i++) {
            CPASYNC16(kd + i * 16, ks + i * 8);
            CPASYNC16(vd + i * 16, vs + i * 8);
        }
        CPCOMMIT();
    }

    for (int t = 0; t < 8; t++) {
        if (t + 1 < 8) {
            int j0 = ((t + 1) * 2 + wg) * 64;
            uint32_t boff = ((t + 1) & 1) * ATT_BUFS;
            const __nv_bfloat16* ks = kg + (size_t)(b * S_ + j0 + ldr) * HD_ + ldc;
            const __nv_bfloat16* vs = vg + (size_t)(b * S_ + j0 + ldr) * HD_ + ldc;
            uint32_t kd = sKS + boff + ldr * 272 + ldc * 2;
            uint32_t vd = sVS + boff + ldr * 272 + ldc * 2;
            #pragma unroll
            for (int i = 0; i < 8; i++) {
                CPASYNC16(kd + i * 16, ks + i * 8);
                CPASYNC16(vd + i * 16, vs + i * 8);
            }
            CPCOMMIT();
            CPWAIT1();
        } else {
            CPWAIT0();
        }
        __syncthreads();
        uint32_t kbuf = sKS + (t & 1) * ATT_BUFS;
        uint32_t vbuf = sVS + (t & 1) * ATT_BUFS;
        int j0 = (t * 2 + wg) * 64;

        float c[8][4];
        #pragma unroll
        for (int nt = 0; nt < 8; nt++)
            #pragma unroll
            for (int j = 0; j < 4; j++) c[nt][j] = 0.f;
        #pragma unroll
        for (int ks = 0; ks < 8; ks++) {
            uint32_t bfd[8][2];
            #pragma unroll
            for (int np = 0; np < 4; np++) {
                uint32_t x0, x1, x2, x3;
                ldsm4(x0, x1, x2, x3,
                      kbuf + (np * 16 + bRow) * 272 + bColB + ks * 32);
                bfd[np * 2][0] = x0;     bfd[np * 2][1] = x1;
                bfd[np * 2 + 1][0] = x2; bfd[np * 2 + 1][1] = x3;
            }
            #pragma unroll
            for (int nt = 0; nt < 8; nt++)
                mma16816(c[nt], qf[ks], bfd[nt]);
        }
        #pragma unroll
        for (int nt = 0; nt < 8; nt++) {
            int j = j0 + nt * 8 + cA;
            int i00 = min(max(j - pos0, -64), 64) + 64;
            int i01 = min(max(j + 1 - pos0, -64), 64) + 64;
            int i10 = min(max(j - pos1, -64), 64) + 64;
            int i11 = min(max(j + 1 - pos1, -64), 64) + 64;
            c[nt][0] += Rl[m0row * 132 + i00];
            c[nt][1] += Rl[m0row * 132 + i01];
            c[nt][2] += Rl[(m0row + 8) * 132 + i10];
            c[nt][3] += Rl[(m0row + 8) * 132 + i11];
        }
        float mx0 = -1e30f, mx1 = -1e30f;
        #pragma unroll
        for (int nt = 0; nt < 8; nt++) {
            mx0 = fmaxf(mx0, fmaxf(c[nt][0], c[nt][1]));
            mx1 = fmaxf(mx1, fmaxf(c[nt][2], c[nt][3]));
        }
        mx0 = fmaxf(mx0, __shfl_xor_sync(0xffffffffu, mx0, 1));
        mx0 = fmaxf(mx0, __shfl_xor_sync(0xffffffffu, mx0, 2));
        mx1 = fmaxf(mx1, __shfl_xor_sync(0xffffffffu, mx1, 1));
        mx1 = fmaxf(mx1, __shfl_xor_sync(0xffffffffu, mx1, 2));
        float mn0 = fmaxf(m_run0, mx0), mn1 = fmaxf(m_run1, mx1);
        float sc0 = __expf(m_run0 - mn0), sc1 = __expf(m_run1 - mn1);
        m_run0 = mn0; m_run1 = mn1;
        float rs0 = 0.f, rs1 = 0.f;
        #pragma unroll
        for (int nt = 0; nt < 8; nt++) {
            c[nt][0] = __expf(c[nt][0] - mn0); rs0 += c[nt][0];
            c[nt][1] = __expf(c[nt][1] - mn0); rs0 += c[nt][1];
            c[nt][2] = __expf(c[nt][2] - mn1); rs1 += c[nt][2];
            c[nt][3] = __expf(c[nt][3] - mn1); rs1 += c[nt][3];
        }
        rs0 += __shfl_xor_sync(0xffffffffu, rs0, 1);
        rs0 += __shfl_xor_sync(0xffffffffu, rs0, 2);
        rs1 += __shfl_xor_sync(0xffffffffu, rs1, 1);
        rs1 += __shfl_xor_sync(0xffffffffu, rs1, 2);
        l_run0 = l_run0 * sc0 + rs0;
        l_run1 = l_run1 * sc1 + rs1;
        #pragma unroll
        for (int nt = 0; nt < 16; nt++) {
            ctx[nt][0] *= sc0; ctx[nt][1] *= sc0;
            ctx[nt][2] *= sc1; ctx[nt][3] *= sc1;
        }
        uint32_t pf[4][4];
        #pragma unroll
        for (int k2 = 0; k2 < 4; k2++) {
            pf[k2][0] = packbf(c[2 * k2][0], c[2 * k2][1]);
            pf[k2][1] = packbf(c[2 * k2][2], c[2 * k2][3]);
            pf[k2][2] = packbf(c[2 * k2 + 1][0], c[2 * k2 + 1][1]);
            pf[k2][3] = packbf(c[2 * k2 + 1][2], c[2 * k2 + 1][3]);
        }
        #pragma unroll
        for (int k2 = 0; k2 < 4; k2++) {
            #pragma unroll
            for (int dp = 0; dp < 8; dp++) {
                uint32_t x0, x1, x2, x3;
                ldsm4t(x0, x1, x2, x3,
                       vbuf + (k2 * 16 + vRow) * 272 + dp * 32 + vColB);
                uint32_t b0[2] = {x0, x1};
                uint32_t b1[2] = {x2, x3};
                mma16816(ctx[2 * dp], pf[k2], b0);
                mma16816(ctx[2 * dp + 1], pf[k2], b1);
            }
        }
        __syncthreads();
    }

    if ((lane & 3) == 0) {
        sM[wg * 64 + m0row] = m_run0;     sL[wg * 64 + m0row] = l_run0;
        sM[wg * 64 + m0row + 8] = m_run1; sL[wg * 64 + m0row + 8] = l_run1;
    }
    __syncthreads();
    float mo0 = sM[(1 - wg) * 64 + m0row];
    float mo1 = sM[(1 - wg) * 64 + m0row + 8];
    float lo0 = sL[(1 - wg) * 64 + m0row];
    float lo1 = sL[(1 - wg) * 64 + m0row + 8];
    float M0 = fmaxf(m_run0, mo0), M1 = fmaxf(m_run1, mo1);
    float s0 = __expf(m_run0 - M0), s1 = __expf(m_run1 - M1);
    float lt0 = l_run0 * s0 + lo0 * __expf(mo0 - M0);
    float lt1 = l_run1 * s1 + lo1 * __expf(mo1 - M1);
    #pragma unroll
    for (int nt = 0; nt < 16; nt++) {
        ctx[nt][0] *= s0; ctx[nt][1] *= s0;
        ctx[nt][2] *= s1; ctx[nt][3] *= s1;
    }
    __syncthreads();
    if (wg == 1) {
        #pragma unroll
        for (int nt = 0; nt < 16; nt++) {
            int col = nt * 8 + cA;
            Rl[m0row * 132 + col]           = ctx[nt][0];
            Rl[m0row * 132 + col + 1]       = ctx[nt][1];
            Rl[(m0row + 8) * 132 + col]     = ctx[nt][2];
            Rl[(m0row + 8) * 132 + col + 1] = ctx[nt][3];
        }
    }
    __syncthreads();
    if (wg == 0) {
        float inv0 = 1.f / lt0, inv1 = 1.f / lt1;
        #pragma unroll
        for (int nt = 0; nt < 16; nt++) {
            int col = nt * 8 + cA;
            float v0 = (ctx[nt][0] + Rl[m0row * 132 + col]) * inv0;
            float v1 = (ctx[nt][1] + Rl[m0row * 132 + col + 1]) * inv0;
            float v2 = (ctx[nt][2] + Rl[(m0row + 8) * 132 + col]) * inv1;
            float v3 = (ctx[nt][3] + Rl[(m0row + 8) * 132 + col + 1]) * inv1;
            *(uint32_t*)(ctxg + (size_t)(gs0 + m0row) * HD_ + col) = packbf(v0, v1);
            *(uint32_t*)(ctxg + (size_t)(gs0 + m0row + 8) * HD_ + col) = packbf(v2, v3);
        }
    }
}

// ---------------------------------------------------------------------------
// Host launcher
// ---------------------------------------------------------------------------
extern "C" void kernel_launch(void* const* d_in, const int* in_sizes, int n_in,
                              void* d_out, int out_size) {
    const float* src  = (const float*)d_in[0];
    const float* ln1w = (const float*)d_in[1];
    const float* ln1b = (const float*)d_in[2];
    const float* ln2w = (const float*)d_in[3];
    const float* ln2b = (const float*)d_in[4];
    const float* agw  = (const float*)d_in[5];
    const float* qw   = (const float*)d_in[6];
    const float* qb   = (const float*)d_in[7];
    const float* kw   = (const float*)d_in[8];
    const float* kb   = (const float*)d_in[9];
    const float* vw   = (const float*)d_in[10];
    const float* vb   = (const float*)d_in[11];
    const float* ow   = (const float*)d_in[12];
    const float* ob   = (const float*)d_in[13];
    const float* rel  = (const float*)d_in[14];
    const float* fgw  = (const float*)d_in[15];
    const float* w1   = (const float*)d_in[16];
    const float* b1   = (const float*)d_in[17];
    const float* w2   = (const float*)d_in[18];
    const float* b2   = (const float*)d_in[19];
    float* out = (float*)d_out;

    float *gwa, *gwf, *kvb;
    int *cnta, *cntf, *lista, *listf;
    __nv_bfloat16 *xnbf, *xn2bf, *qbf, *kvbf, *ctxbf, *hbf, *yabf, *wbf;
    cudaGetSymbolAddress((void**)&gwa,   g_gwa);
    cudaGetSymbolAddress((void**)&gwf,   g_gwf);
    cudaGetSymbolAddress((void**)&kvb,   g_kvb);
    cudaGetSymbolAddress((void**)&cnta,  g_cnt_a);
    cudaGetSymbolAddress((void**)&cntf,  g_cnt_f);
    cudaGetSymbolAddress((void**)&lista, g_list_a);
    cudaGetSymbolAddress((void**)&listf, g_list_f);
    cudaGetSymbolAddress((void**)&xnbf,  g_xn_bf);
    cudaGetSymbolAddress((void**)&xn2bf, g_xn2_bf);
    cudaGetSymbolAddress((void**)&qbf,   g_q_bf);
    cudaGetSymbolAddress((void**)&kvbf,  g_kv_bf);
    cudaGetSymbolAddress((void**)&ctxbf, g_ctx_bf);
    cudaGetSymbolAddress((void**)&hbf,   g_h_bf);
    cudaGetSymbolAddress((void**)&yabf,  g_ya_bf);
    cudaGetSymbolAddress((void**)&wbf,   g_wbf);

    __nv_bfloat16* w1t  = wbf + WSEG_W1;
    __nv_bfloat16* w2t  = wbf + WSEG_W2;
    __nv_bfloat16* qwt  = wbf + WSEG_QW;
    __nv_bfloat16* owt  = wbf + WSEG_OW;
    __nv_bfloat16* kvwt = wbf + WSEG_KW;

    static cudaStream_t s1 = nullptr;
    static cudaEvent_t ev_fork = nullptr, ev_join = nullptr;
    static bool attr_set = []() {
        cudaFuncSetAttribute(attn_mma_k,
                             cudaFuncAttributeMaxDynamicSharedMemorySize,
                             ATT2_SMEM);
        cudaFuncSetAttribute(qkv_k,
                             cudaFuncAttributeMaxDynamicSharedMemorySize, GEMM_SMEM_BM64);
        cudaFuncSetAttribute(mmasync_gemm_k<HD_, 64, false, false, true, true, false>,
                             cudaFuncAttributeMaxDynamicSharedMemorySize, GEMM_SMEM_BM64);
        cudaFuncSetAttribute(mmasync_gemm_k<D_, 128, true, true, false, true, false>,
                             cudaFuncAttributeMaxDynamicSharedMemorySize, GEMM_SMEM_BM128);
        cudaFuncSetAttribute(mmasync_gemm_k<FH_, 128, false, false, true, false, true>,
                             cudaFuncAttributeMaxDynamicSharedMemorySize, GEMM_SMEM_BM128);
        return true;
    }();
    (void)attr_set;
    if (!s1) {
        cudaStreamCreateWithFlags(&s1, cudaStreamNonBlocking);
        cudaEventCreateWithFlags(&ev_fork, cudaEventDisableTiming);
        cudaEventCreateWithFlags(&ev_join, cudaEventDisableTiming);
    }

    // fork: weight conversion on side stream, concurrent with setup+ln1
    cudaEventRecord(ev_fork, 0);
    cudaStreamWaitEvent(s1, ev_fork, 0);
    conv_all_k<<<(WSEG_END / 4 + 255) / 256, 256, 0, s1>>>(w1, w2, qw, ow, kw, vw);
    cudaEventRecord(ev_join, s1);

    setup_k<<<(2 * CAP_) / 256, 256>>>(kb, vb);
    ln1_k<<<NTOK_, 256>>>(src, ln1w, ln1b, agw, xnbf);

    cudaStreamWaitEvent(0, ev_join, 0);

    // fused K/V + Q projection
    qkv_k<<<dim3(1, NTOK_ / 64, 2 + EA_), 256, GEMM_SMEM_BM64>>>(
        xnbf, kvwt, qwt, kvb, qb, kvbf, qbf, lista, cnta,
        0.08838834764831845f);

    // flash attention (double-buffered)
    attn_mma_k<<<NTS_ / 64, 256, ATT2_SMEM>>>(
        qbf, kvbf, kvbf + (size_t)NTOK_ * HD_, rel, ctxbf);

    // per-expert output projection, gated (bf16 out), BM=64
    mmasync_gemm_k<HD_, 64, false, false, true, true, false>
        <<<dim3(D_ / 128, CAP_ / 64, EA_), 256, GEMM_SMEM_BM64>>>(
        ctxbf, owt, ob, D_, (void*)yabf, D_, 0,
        lista, cnta, gwa, 1.f);

    // residual + LN2 + FFN router; residual -> out
    combine_ln2_k<<<NTOK_, 256>>>(src, yabf, ln2w, ln2b, fgw, out, xn2bf);

    // FFN, BM=128: w1 (relu -> bf16 h), w2 accumulates into out (red.v2)
    mmasync_gemm_k<D_, 128, true, true, false, true, false>
        <<<dim3(FH_ / 128, CAP_ / 128, EF_), 256, GEMM_SMEM_BM128>>>(
        xn2bf, w1t, b1, FH_, (void*)hbf, FH_, 0,
        listf, cntf, nullptr, 1.f);
    mmasync_gemm_k<FH_, 128, false, false, true, false, true>
        <<<dim3(D_ / 128, CAP_ / 128, EF_), 256, GEMM_SMEM_BM128>>>(
        hbf, w2t, b2, D_, (void*)out, D_, 0,
        listf, cntf, gwf, 1.f);
}

// round 17
// speedup vs baseline: 1.0403x; 1.0066x over previous
#include <cuda_runtime.h>
#include <cuda_bf16.h>
#include <math.h>
#include <stdint.h>

// ---------------------------------------------------------------------------
// Problem constants
// ---------------------------------------------------------------------------
#define D_    1024
#define HD_   128
#define EA_   8
#define EF_   16
#define FH_   512
#define S_    1024
#define B_    4
#define NTOK_ 4096
#define NTS_  8192
#define CAP_  4096

#define WSEG_W1 0
#define WSEG_W2 8388608
#define WSEG_QW 16777216
#define WSEG_OW 17825792
#define WSEG_KW 18874368
#define WSEG_VW 19005440
#define WSEG_END 19136512

// ---------------------------------------------------------------------------
// PTX helpers
// ---------------------------------------------------------------------------
__device__ __forceinline__ uint32_t smem_to_u32(const void* p) {
    uint32_t a;
    asm("{ .reg .u64 t; cvta.to.shared.u64 t, %1; cvt.u32.u64 %0, t; }"
        : "=r"(a) : "l"(p));
    return a;
}
__device__ __forceinline__ void ldsm4(uint32_t& r0, uint32_t& r1,
                                      uint32_t& r2, uint32_t& r3, uint32_t a) {
    asm volatile("ldmatrix.sync.aligned.m8n8.x4.shared.b16 {%0,%1,%2,%3}, [%4];"
                 : "=r"(r0), "=r"(r1), "=r"(r2), "=r"(r3) : "r"(a));
}
__device__ __forceinline__ void ldsm4t(uint32_t& r0, uint32_t& r1,
                                       uint32_t& r2, uint32_t& r3, uint32_t a) {
    asm volatile("ldmatrix.sync.aligned.m8n8.x4.trans.shared.b16 {%0,%1,%2,%3}, [%4];"
                 : "=r"(r0), "=r"(r1), "=r"(r2), "=r"(r3) : "r"(a));
}
__device__ __forceinline__ void mma16816(float* c, const uint32_t* a,
                                         const uint32_t* b) {
    asm volatile(
        "mma.sync.aligned.m16n8k16.row.col.f32.bf16.bf16.f32 "
        "{%0,%1,%2,%3}, {%4,%5,%6,%7}, {%8,%9}, {%0,%1,%2,%3};"
        : "+f"(c[0]), "+f"(c[1]), "+f"(c[2]), "+f"(c[3])
        : "r"(a[0]), "r"(a[1]), "r"(a[2]), "r"(a[3]), "r"(b[0]), "r"(b[1]));
}
__device__ __forceinline__ uint32_t packbf(float a, float b) {
    __nv_bfloat162 p = __floats2bfloat162_rn(a, b);
    return *(uint32_t*)&p;
}
__device__ __forceinline__ void redv2(float* p, float v0, float v1) {
    asm volatile("red.global.add.v2.f32 [%0], {%1, %2};"
                 :: "l"(p), "f"(v0), "f"(v1) : "memory");
}
#define CPASYNC16(dst, src) \
    asm volatile("cp.async.cg.shared.global [%0], [%1], 16;" \
                 :: "r"(dst), "l"(src))
#define CPCOMMIT() asm volatile("cp.async.commit_group;" ::: "memory")
#define CPWAIT1()  asm volatile("cp.async.wait_group 1;" ::: "memory")
#define CPWAIT0()  asm volatile("cp.async.wait_group 0;" ::: "memory")

// ---------------------------------------------------------------------------
// Device-global scratch
// ---------------------------------------------------------------------------
__device__ float g_gwa [NTS_];
__device__ float g_gwf [NTS_];
__device__ int   g_cnt_a [EA_];
__device__ int   g_cnt_f [EF_];
__device__ int   g_list_a[EA_ * CAP_];
__device__ int   g_list_f[EF_ * CAP_];
__device__ int   g_list_id[CAP_];
__device__ float g_kvb [2 * HD_];
__device__ __nv_bfloat16 g_xn_bf [NTOK_ * D_];
__device__ __nv_bfloat16 g_xn2_bf[NTOK_ * D_];
__device__ __nv_bfloat16 g_q_bf  [NTS_  * HD_];
__device__ __nv_bfloat16 g_kv_bf [2 * NTOK_ * HD_];
__device__ __nv_bfloat16 g_ctx_bf[NTS_  * HD_];
__device__ __nv_bfloat16 g_h_bf  [NTS_  * FH_];
__device__ __nv_bfloat16 g_ya_bf [NTS_  * D_];
__device__ __nv_bfloat16 g_wbf [WSEG_END];

// ---------------------------------------------------------------------------
// Setup
// ---------------------------------------------------------------------------
__global__ void __launch_bounds__(256) setup_k(const float* __restrict__ kb,
                                               const float* __restrict__ vb) {
    int i = blockIdx.x * 256 + threadIdx.x;
    if (i < EA_) g_cnt_a[i] = 0;
    if (i < EF_) g_cnt_f[i] = 0;
    if (i < CAP_) g_list_id[i] = i;
    if (i < HD_) g_kvb[i] = kb[i];
    else if (i >= CAP_ && i < CAP_ + HD_) g_kvb[HD_ + i - CAP_] = vb[i - CAP_];
}

// ---------------------------------------------------------------------------
// Flat fp32->bf16 weight convert
// ---------------------------------------------------------------------------
__global__ void __launch_bounds__(256) conv_all_k(
    const float* __restrict__ w1, const float* __restrict__ w2,
    const float* __restrict__ qw, const float* __restrict__ ow,
    const float* __restrict__ kw, const float* __restrict__ vw)
{
    size_t el = ((size_t)blockIdx.x * 256 + threadIdx.x) * 4;
    if (el >= WSEG_END) return;
    const float* src;
    if (el < WSEG_W2)      src = w1 + (el - WSEG_W1);
    else if (el < WSEG_QW) src = w2 + (el - WSEG_W2);
    else if (el < WSEG_OW) src = qw + (el - WSEG_QW);
    else if (el < WSEG_KW) src = ow + (el - WSEG_OW);
    else if (el < WSEG_VW) src = kw + (el - WSEG_KW);
    else                   src = vw + (el - WSEG_VW);
    float4 v = *(const float4*)src;
    uint2 st;
    st.x = packbf(v.x, v.y); st.y = packbf(v.z, v.w);
    *(uint2*)(g_wbf + el) = st;
}

// ---------------------------------------------------------------------------
// LayerNorm 1 + attention router fused
// ---------------------------------------------------------------------------
__global__ void __launch_bounds__(256) ln1_k(
    const float* __restrict__ x, const float* __restrict__ w,
    const float* __restrict__ b, const float* __restrict__ gwm,
    __nv_bfloat16* __restrict__ ybf)
{
    int t = blockIdx.x, tid = threadIdx.x;
    int lane = tid & 31, wrp = tid >> 5;
    float4 v = ((const float4*)(x + (size_t)t * D_))[tid];
    float s = v.x + v.y + v.z + v.w;
    float q = fmaf(v.x, v.x, fmaf(v.y, v.y, fmaf(v.z, v.z, v.w * v.w)));
    __shared__ float ss[8], sq[8];
    __shared__ float sp[8][EA_];
    #pragma unroll
    for (int o = 16; o; o >>= 1) {
        s += __shfl_xor_sync(0xffffffffu, s, o);
        q += __shfl_xor_sync(0xffffffffu, q, o);
    }
    if (lane == 0) { ss[wrp] = s; sq[wrp] = q; }
    __syncthreads();
    if (tid == 0) {
        float a = 0.f, c = 0.f;
        #pragma unroll
        for (int i = 0; i < 8; i++) { a += ss[i]; c += sq[i]; }
        ss[0] = a; sq[0] = c;
    }
    __syncthreads();
    float mu  = ss[0] * (1.f / D_);
    float var = sq[0] * (1.f / D_) - mu * mu;
    float rs  = rsqrtf(var + 1e-5f);
    float4 wv = ((const float4*)w)[tid];
    float4 bv = ((const float4*)b)[tid];
    float o0 = (v.x - mu) * rs * wv.x + bv.x;
    float o1 = (v.y - mu) * rs * wv.y + bv.y;
    float o2 = (v.z - mu) * rs * wv.z + bv.z;
    float o3 = (v.w - mu) * rs * wv.w + bv.w;
    uint2 st;
    st.x = packbf(o0, o1); st.y = packbf(o2, o3);
    *(uint2*)(ybf + (size_t)t * D_ + tid * 4) = st;

    float p[EA_];
    #pragma unroll
    for (int e = 0; e < EA_; e++) p[e] = 0.f;
    float xs[4] = {o0, o1, o2, o3};
    const float4* g4 = (const float4*)(gwm + (size_t)(tid * 4) * EA_);
    #pragma unroll
    for (int j = 0; j < 4; j++) {
        float4 ga = g4[j * 2], gb = g4[j * 2 + 1];
        p[0] = fmaf(xs[j], ga.x, p[0]); p[1] = fmaf(xs[j], ga.y, p[1]);
        p[2] = fmaf(xs[j], ga.z, p[2]); p[3] = fmaf(xs[j], ga.w, p[3]);
        p[4] = fmaf(xs[j], gb.x, p[4]); p[5] = fmaf(xs[j], gb.y, p[5]);
        p[6] = fmaf(xs[j], gb.z, p[6]); p[7] = fmaf(xs[j], gb.w, p[7]);
    }
    #pragma unroll
    for (int e = 0; e < EA_; e++)
        #pragma unroll
        for (int o = 16; o; o >>= 1)
            p[e] += __shfl_xor_sync(0xffffffffu, p[e], o);
    if (lane == 0)
        #pragma unroll
        for (int e = 0; e < EA_; e++) sp[wrp][e] = p[e];
    __syncthreads();
    if (tid == 0) {
        float l[EA_];
        #pragma unroll
        for (int e = 0; e < EA_; e++) {
            float a = 0.f;
            #pragma unroll
            for (int wdx = 0; wdx < 8; wdx++) a += sp[wdx][e];
            l[e] = a;
        }
        int i0 = 0; float v0 = l[0];
        #pragma unroll
        for (int e = 1; e < EA_; e++) if (l[e] > v0) { v0 = l[e]; i0 = e; }
        int i1 = -1; float v1 = -1e30f;
        #pragma unroll
        for (int e = 0; e < EA_; e++)
            if (e != i0 && l[e] > v1) { v1 = l[e]; i1 = e; }
        float e1 = __expf(v1 - v0);
        float inv = 1.f / (1.f + e1);
        g_gwa[2 * t]     = inv;
        g_gwa[2 * t + 1] = e1 * inv;
        int p0 = atomicAdd(&g_cnt_a[i0], 1);
        g_list_a[i0 * CAP_ + p0] = 2 * t;
        int p1 = atomicAdd(&g_cnt_a[i1], 1);
        g_list_a[i1 * CAP_ + p1] = 2 * t + 1;
    }
}

// ---------------------------------------------------------------------------
// Residual-add (ya bf16) + LayerNorm 2 + FFN router fused; residual -> out
// ---------------------------------------------------------------------------
__global__ void __launch_bounds__(256) combine_ln2_k(
    const float* __restrict__ src, const __nv_bfloat16* __restrict__ ya,
    const float* __restrict__ w, const float* __restrict__ b,
    const float* __restrict__ gwm,
    float* __restrict__ out, __nv_bfloat16* __restrict__ xn2bf)
{
    int t = blockIdx.x, tid = threadIdx.x;
    int lane = tid & 31, wrp = tid >> 5;
    float4 v  = ((const float4*)(src + (size_t)t * D_))[tid];
    uint2 u0 = *(const uint2*)(ya + (size_t)(2 * t) * D_ + tid * 4);
    uint2 u1 = *(const uint2*)(ya + (size_t)(2 * t + 1) * D_ + tid * 4);
    {
        __nv_bfloat162 a0 = *(__nv_bfloat162*)&u0.x;
        __nv_bfloat162 a1 = *(__nv_bfloat162*)&u0.y;
        __nv_bfloat162 b0 = *(__nv_bfloat162*)&u1.x;
        __nv_bfloat162 b1 = *(__nv_bfloat162*)&u1.y;
        v.x += __bfloat162float(a0.x) + __bfloat162float(b0.x);
        v.y += __bfloat162float(a0.y) + __bfloat162float(b0.y);
        v.z += __bfloat162float(a1.x) + __bfloat162float(b1.x);
        v.w += __bfloat162float(a1.y) + __bfloat162float(b1.y);
    }
    ((float4*)(out + (size_t)t * D_))[tid] = v;

    float s = v.x + v.y + v.z + v.w;
    float q = fmaf(v.x, v.x, fmaf(v.y, v.y, fmaf(v.z, v.z, v.w * v.w)));
    __shared__ float ss[8], sq[8];
    __shared__ float sp[8][EF_];
    #pragma unroll
    for (int o = 16; o; o >>= 1) {
        s += __shfl_xor_sync(0xffffffffu, s, o);
        q += __shfl_xor_sync(0xffffffffu, q, o);
    }
    if (lane == 0) { ss[wrp] = s; sq[wrp] = q; }
    __syncthreads();
    if (tid == 0) {
        float a = 0.f, c = 0.f;
        #pragma unroll
        for (int i = 0; i < 8; i++) { a += ss[i]; c += sq[i]; }
        ss[0] = a; sq[0] = c;
    }
    __syncthreads();
    float mu  = ss[0] * (1.f / D_);
    float var = sq[0] * (1.f / D_) - mu * mu;
    float rs  = rsqrtf(var + 1e-5f);
    float4 wv = ((const float4*)w)[tid];
    float4 bv = ((const float4*)b)[tid];
    float o0 = (v.x - mu) * rs * wv.x + bv.x;
    float o1 = (v.y - mu) * rs * wv.y + bv.y;
    float o2 = (v.z - mu) * rs * wv.z + bv.z;
    float o3 = (v.w - mu) * rs * wv.w + bv.w;
    uint2 st;
    st.x = packbf(o0, o1); st.y = packbf(o2, o3);
    *(uint2*)(xn2bf + (size_t)t * D_ + tid * 4) = st;

    float p[EF_];
    #pragma unroll
    for (int e = 0; e < EF_; e++) p[e] = 0.f;
    float xs[4] = {o0, o1, o2, o3};
    const float4* g4 = (const float4*)(gwm + (size_t)(tid * 4) * EF_);
    #pragma unroll
    for (int j = 0; j < 4; j++) {
        #pragma unroll
        for (int g = 0; g < 4; g++) {
            float4 gv = g4[j * 4 + g];
            p[g*4+0] = fmaf(xs[j], gv.x, p[g*4+0]);
            p[g*4+1] = fmaf(xs[j], gv.y, p[g*4+1]);
            p[g*4+2] = fmaf(xs[j], gv.z, p[g*4+2]);
            p[g*4+3] = fmaf(xs[j], gv.w, p[g*4+3]);
        }
    }
    #pragma unroll
    for (int e = 0; e < EF_; e++)
        #pragma unroll
        for (int o = 16; o; o >>= 1)
            p[e] += __shfl_xor_sync(0xffffffffu, p[e], o);
    if (lane == 0)
        #pragma unroll
        for (int e = 0; e < EF_; e++) sp[wrp][e] = p[e];
    __syncthreads();
    if (tid == 0) {
        float l[EF_];
        #pragma unroll
        for (int e = 0; e < EF_; e++) {
            float a = 0.f;
            #pragma unroll
            for (int wdx = 0; wdx < 8; wdx++) a += sp[wdx][e];
            l[e] = a;
        }
        int i0 = 0; float v0 = l[0];
        #pragma unroll
        for (int e = 1; e < EF_; e++) if (l[e] > v0) { v0 = l[e]; i0 = e; }
        int i1 = -1; float v1 = -1e30f;
        #pragma unroll
        for (int e = 0; e < EF_; e++)
            if (e != i0 && l[e] > v1) { v1 = l[e]; i1 = e; }
        float e1 = __expf(v1 - v0);
        float inv = 1.f / (1.f + e1);
        g_gwf[2 * t]     = inv;
        g_gwf[2 * t + 1] = e1 * inv;
        int p0 = atomicAdd(&g_cnt_f[i0], 1);
        g_list_f[i0 * CAP_ + p0] = 2 * t;
        int p1 = atomicAdd(&g_cnt_f[i1], 1);
        g_list_f[i1 * CAP_ + p1] = 2 * t + 1;
    }
}

// ---------------------------------------------------------------------------
// Generic grouped GEMM, 3-stage cp.async ring, ONE barrier per stage.
// ---------------------------------------------------------------------------
#define LDAB 72
#define LDB_ 136

template<int KTOT, int BM, bool TOKROW, bool RELU, bool GATE, bool OUTBF, bool ACCUM>
__global__ void __launch_bounds__(256) mmasync_gemm_k(
    const __nv_bfloat16* __restrict__ Abase,
    const __nv_bfloat16* __restrict__ Bbase,
    const float* __restrict__ biasb, int Nfull,
    void* __restrict__ Yv, int ldy, size_t eStrideY,
    const int* __restrict__ lists, const int* __restrict__ cnts,
    const float* __restrict__ gw, float scale)
{
    constexpr int MWARPS = BM / 32;
    constexpr int NWARPS = 8 / MWARPS;
    constexpr int WN     = 128 / NWARPS;
    constexpr int NT     = WN / 8;
    constexpr int A_CH   = BM * 8 / 256;
    constexpr int ASTG   = BM * LDAB * 2;
    constexpr int STAGE  = ASTG + 64 * LDB_ * 2;

    int e = blockIdx.z;
    int cnt = cnts[e];
    int row0 = blockIdx.y * BM;
    if (row0 >= cnt) return;
    int n0 = blockIdx.x * 128;
    const int* list = lists + e * CAP_;

    extern __shared__ char dynsm[];
    __shared__ float bias_s[128];
    __shared__ float gate_s[BM];
    __shared__ int   slot_s[BM];

    int tid = threadIdx.x;
    int wid = tid >> 5, lane = tid & 31;

    if (tid < 128) bias_s[tid] = biasb[(size_t)e * Nfull + n0 + tid];
    if (tid < BM) {
        int r = min(row0 + tid, cnt - 1);
        int sl = list[r];
        slot_s[tid] = sl;
        gate_s[tid] = GATE ? gw[sl] : 1.f;
    }

    uint32_t sBase = smem_to_u32(dynsm);
    uint32_t sA0 = sBase;
    uint32_t sB0 = sBase + ASTG;

    const __nv_bfloat16* Bexp = Bbase + (size_t)e * Nfull * KTOT;
    const __nv_bfloat16* aSrc[A_CH];
    uint32_t aDst[A_CH];
    #pragma unroll
    for (int i = 0; i < A_CH; i++) {
        int idx = tid + i * 256;
        int am = idx >> 3, ac = idx & 7;
        int r = min(row0 + am, cnt - 1);
        int sl = list[r];
        int gr = TOKROW ? (sl >> 1) : sl;
        aSrc[i] = Abase + (size_t)gr * KTOT + ac * 8;
        aDst[i] = sA0 + (am * LDAB + ac * 8) * 2;
    }
    const __nv_bfloat16* bSrc[4];
    uint32_t bDst[4];
    #pragma unroll
    for (int i = 0; i < 4; i++) {
        int idx = tid + i * 256;
        int bk = idx >> 4, bn = (idx & 15) * 8;
        bSrc[i] = Bexp + (size_t)bk * Nfull + n0 + bn;
        bDst[i] = sB0 + (bk * LDB_ + bn) * 2;
    }

    int warpM = (wid % MWARPS) * 32;
    int warpN = (wid / MWARPS) * WN;
    uint32_t aAddr = sA0 + ((warpM + (lane & 15)) * LDAB + (lane >> 4) * 8) * 2;
    uint32_t bAddrBase = sB0 + ((lane & 15) * LDB_ + warpN + (lane >> 4) * 8) * 2;

    float acc[2][NT][4];
    #pragma unroll
    for (int mt = 0; mt < 2; mt++)
        #pragma unroll
        for (int nt = 0; nt < NT; nt++)
            #pragma unroll
            for (int j = 0; j < 4; j++) acc[mt][nt][j] = 0.f;

    const int NSTAGE = KTOT / 64;

    // prologue: stages 0 and 1
    #pragma unroll
    for (int i = 0; i < A_CH; i++) CPASYNC16(aDst[i], aSrc[i]);
    #pragma unroll
    for (int i = 0; i < 4; i++) CPASYNC16(bDst[i], bSrc[i]);
    CPCOMMIT();
    if (NSTAGE > 1) {
        #pragma unroll
        for (int i = 0; i < A_CH; i++) CPASYNC16(aDst[i] + STAGE, aSrc[i] + 64);
        #pragma unroll
        for (int i = 0; i < 4; i++)
            CPASYNC16(bDst[i] + STAGE, bSrc[i] + (size_t)64 * Nfull);
        CPCOMMIT();
    }

    for (int st = 0; st < NSTAGE; st++) {
        if (st + 1 < NSTAGE) CPWAIT1(); else CPWAIT0();
        __syncthreads();
        uint32_t off = (st % 3) * STAGE;
        #pragma unroll
        for (int kk = 0; kk < 4; kk++) {
            uint32_t a[2][4];
            ldsm4(a[0][0], a[0][1], a[0][2], a[0][3], aAddr + off + kk * 32);
            ldsm4(a[1][0], a[1][1], a[1][2], a[1][3],
                  aAddr + off + 16 * LDAB * 2 + kk * 32);
            uint32_t b[NT][2];
            #pragma unroll
            for (int np = 0; np < NT / 2; np++) {
                uint32_t r0, r1, r2, r3;
                ldsm4t(r0, r1, r2, r3,
                       bAddrBase + off + kk * (16 * LDB_ * 2) + np * 32);
                b[np * 2][0] = r0;     b[np * 2][1] = r1;
                b[np * 2 + 1][0] = r2; b[np * 2 + 1][1] = r3;
            }
            #pragma unroll
            for (int mt = 0; mt < 2; mt++)
                #pragma unroll
                for (int nt = 0; nt < NT; nt++)
                    mma16816(acc[mt][nt], a[mt], b[nt]);
        }
        if (st + 2 < NSTAGE) {
            uint32_t boff = ((st + 2) % 3) * STAGE;
            int k0 = (st + 2) * 64;
            #pragma unroll
            for (int i = 0; i < A_CH; i++) CPASYNC16(aDst[i] + boff, aSrc[i] + k0);
            #pragma unroll
            for (int i = 0; i < 4; i++)
                CPASYNC16(bDst[i] + boff, bSrc[i] + (size_t)k0 * Nfull);
            CPCOMMIT();
        }
    }

    int lane4 = lane >> 2;
    int lcol  = (lane & 3) * 2;
    #pragma unroll
    for (int mt = 0; mt < 2; mt++) {
        #pragma unroll
        for (int h = 0; h < 2; h++) {
            int m = warpM + mt * 16 + lane4 + h * 8;
            if (row0 + m >= cnt) continue;
            int sl = slot_s[m];
            float f = gate_s[m];
            int orow = ACCUM ? (sl >> 1) : sl;
            size_t ybase = (size_t)e * eStrideY + (size_t)orow * ldy + n0;
            #pragma unroll
            for (int nt = 0; nt < NT; nt++) {
                int col = warpN + nt * 8 + lcol;
                float v0 = (acc[mt][nt][h * 2 + 0] + bias_s[col]) * scale;
                float v1 = (acc[mt][nt][h * 2 + 1] + bias_s[col + 1]) * scale;
                if (RELU) { v0 = fmaxf(v0, 0.f); v1 = fmaxf(v1, 0.f); }
                v0 *= f; v1 *= f;
                if (ACCUM) {
                    redv2((float*)Yv + ybase + col, v0, v1);
                } else if (OUTBF) {
                    *(uint32_t*)((__nv_bfloat16*)Yv + ybase + col) = packbf(v0, v1);
                } else {
                    float2 p = make_float2(v0, v1);
                    *(float2*)((float*)Yv + ybase + col) = p;
                }
            }
        }
    }
}

#define GEMM_SMEM_BM64  (3 * (64 * LDAB * 2 + 64 * LDB_ * 2))
#define GEMM_SMEM_BM128 (3 * (128 * LDAB * 2 + 64 * LDB_ * 2))

// ---------------------------------------------------------------------------
// Fused K/V + Q projection — 3-stage ring, ONE barrier per stage
// ---------------------------------------------------------------------------
__global__ void __launch_bounds__(256) qkv_k(
    const __nv_bfloat16* __restrict__ Abase,
    const __nv_bfloat16* __restrict__ kvw,
    const __nv_bfloat16* __restrict__ qwv,
    const float* __restrict__ kvb2,
    const float* __restrict__ qb,
    __nv_bfloat16* __restrict__ kvout,
    __nv_bfloat16* __restrict__ qout,
    const int* __restrict__ lista,
    const int* __restrict__ cnta,
    float qscale)
{
    constexpr int BM = 64, NT = 4;
    constexpr int ASTG  = BM * LDAB * 2;
    constexpr int STAGE = ASTG + 64 * LDB_ * 2;
    const int KTOT = D_, NSTAGE = D_ / 64;

    int z = blockIdx.z;
    bool isQ = (z >= 2);
    int e = isQ ? (z - 2) : z;
    int cnt = isQ ? cnta[e] : NTOK_;
    int row0 = blockIdx.y * BM;
    if (row0 >= cnt) return;
    const int* list = isQ ? (lista + e * CAP_) : g_list_id;
    const __nv_bfloat16* Bexp = (isQ ? qwv : kvw) + (size_t)e * HD_ * D_;
    const float* bias = (isQ ? qb : kvb2) + (size_t)e * HD_;
    float scale = isQ ? qscale : 1.f;
    __nv_bfloat16* Yp = isQ ? qout : (kvout + (size_t)e * NTOK_ * HD_);

    extern __shared__ char dynsm[];
    __shared__ float bias_s[128];
    __shared__ int   slot_s[BM];

    int tid = threadIdx.x;
    int wid = tid >> 5, lane = tid & 31;

    if (tid < 128) bias_s[tid] = bias[tid];
    if (tid < BM) {
        int r = min(row0 + tid, cnt - 1);
        slot_s[tid] = list[r];
    }

    uint32_t sBase = smem_to_u32(dynsm);
    uint32_t sA0 = sBase;
    uint32_t sB0 = sBase + ASTG;

    const __nv_bfloat16* aSrc[2];
    uint32_t aDst[2];
    #pragma unroll
    for (int i = 0; i < 2; i++) {
        int idx = tid + i * 256;
        int am = idx >> 3, ac = idx & 7;
        int r = min(row0 + am, cnt - 1);
        int sl = list[r];
        int gr = isQ ? (sl >> 1) : sl;
        aSrc[i] = Abase + (size_t)gr * KTOT + ac * 8;
        aDst[i] = sA0 + (am * LDAB + ac * 8) * 2;
    }
    const __nv_bfloat16* bSrc[4];
    uint32_t bDst[4];
    #pragma unroll
    for (int i = 0; i < 4; i++) {
        int idx = tid + i * 256;
        int bk = idx >> 4, bn = (idx & 15) * 8;
        bSrc[i] = Bexp + (size_t)bk * HD_ + bn;
        bDst[i] = sB0 + (bk * LDB_ + bn) * 2;
    }

    int warpM = (wid & 1) * 32;
    int warpN = (wid >> 1) * 32;
    uint32_t aAddr = sA0 + ((warpM + (lane & 15)) * LDAB + (lane >> 4) * 8) * 2;
    uint32_t bAddrBase = sB0 + ((lane & 15) * LDB_ + warpN + (lane >> 4) * 8) * 2;

    float acc[2][NT][4];
    #pragma unroll
    for (int mt = 0; mt < 2; mt++)
        #pragma unroll
        for (int nt = 0; nt < NT; nt++)
            #pragma unroll
            for (int j = 0; j < 4; j++) acc[mt][nt][j] = 0.f;

    #pragma unroll
    for (int i = 0; i < 2; i++) CPASYNC16(aDst[i], aSrc[i]);
    #pragma unroll
    for (int i = 0; i < 4; i++) CPASYNC16(bDst[i], bSrc[i]);
    CPCOMMIT();
    #pragma unroll
    for (int i = 0; i < 2; i++) CPASYNC16(aDst[i] + STAGE, aSrc[i] + 64);
    #pragma unroll
    for (int i = 0; i < 4; i++)
        CPASYNC16(bDst[i] + STAGE, bSrc[i] + (size_t)64 * HD_);
    CPCOMMIT();

    for (int st = 0; st < NSTAGE; st++) {
        if (st + 1 < NSTAGE) CPWAIT1(); else CPWAIT0();
        __syncthreads();
        uint32_t off = (st % 3) * STAGE;
        #pragma unroll
        for (int kk = 0; kk < 4; kk++) {
            uint32_t a[2][4];
            ldsm4(a[0][0], a[0][1], a[0][2], a[0][3], aAddr + off + kk * 32);
            ldsm4(a[1][0], a[1][1], a[1][2], a[1][3],
                  aAddr + off + 16 * LDAB * 2 + kk * 32);
            uint32_t b[NT][2];
            #pragma unroll
            for (int np = 0; np < NT / 2; np++) {
                uint32_t r0, r1, r2, r3;
                ldsm4t(r0, r1, r2, r3,
                       bAddrBase + off + kk * (16 * LDB_ * 2) + np * 32);
                b[np * 2][0] = r0;     b[np * 2][1] = r1;
                b[np * 2 + 1][0] = r2; b[np * 2 + 1][1] = r3;
            }
            #pragma unroll
            for (int mt = 0; mt < 2; mt++)
                #pragma unroll
                for (int nt = 0; nt < NT; nt++)
                    mma16816(acc[mt][nt], a[mt], b[nt]);
        }
        if (st + 2 < NSTAGE) {
            uint32_t boff = ((st + 2) % 3) * STAGE;
            int k0 = (st + 2) * 64;
            #pragma unroll
            for (int i = 0; i < 2; i++) CPASYNC16(aDst[i] + boff, aSrc[i] + k0);
            #pragma unroll
            for (int i = 0; i < 4; i++)
                CPASYNC16(bDst[i] + boff, bSrc[i] + (size_t)k0 * HD_);
            CPCOMMIT();
        }
    }

    int lane4 = lane >> 2;
    int lcol  = (lane & 3) * 2;
    #pragma unroll
    for (int mt = 0; mt < 2; mt++) {
        #pragma unroll
        for (int h = 0; h < 2; h++) {
            int m = warpM + mt * 16 + lane4 + h * 8;
            if (row0 + m >= cnt) continue;
            int sl = slot_s[m];
            #pragma unroll
            for (int nt = 0; nt < NT; nt++) {
                int col = warpN + nt * 8 + lcol;
                float v0 = (acc[mt][nt][h * 2 + 0] + bias_s[col]) * scale;
                float v1 = (acc[mt][nt][h * 2 + 1] + bias_s[col + 1]) * scale;
                *(uint32_t*)(Yp + (size_t)sl * HD_ + col) = packbf(v0, v1);
            }
        }
    }
}

// ---------------------------------------------------------------------------
// Tensor-core flash attention — K/V cp.async double-buffered
// ---------------------------------------------------------------------------
#define ATT2_QS   0
#define ATT2_KS   17408
#define ATT2_VS   87040
#define ATT2_RL   156672
#define ATT2_SM   190464
#define ATT2_SL   190976
#define ATT2_SMEM 191488
#define ATT_WGS   34816
#define ATT_BUFS  17408

__global__ void __launch_bounds__(256) attn_mma_k(
    const __nv_bfloat16* __restrict__ qg,
    const __nv_bfloat16* __restrict__ kg,
    const __nv_bfloat16* __restrict__ vg,
    const float* __restrict__ rel,
    __nv_bfloat16* __restrict__ ctxg)
{
    extern __shared__ char smraw[];
    __nv_bfloat16* Qs = (__nv_bfloat16*)(smraw + ATT2_QS);
    float* Rl = (float*)(smraw + ATT2_RL);
    float* sM = (float*)(smraw + ATT2_SM);
    float* sL = (float*)(smraw + ATT2_SL);

    int tid = threadIdx.x;
    int wid = tid >> 5, lane = tid & 31;
    int wg = wid >> 2, ww = wid & 3;
    int t128 = tid & 127;

    int gs0 = blockIdx.x * 64;
    int b   = gs0 >> 11;
    int ls0 = gs0 & 2047;

    {
        int r = tid >> 2, cb = (tid & 3) * 32;
        const uint4* src = (const uint4*)(qg + (size_t)(gs0 + r) * HD_ + cb);
        uint4* dst = (uint4*)(smraw + ATT2_QS + r * 272 + cb * 2);
        #pragma unroll
        for (int i = 0; i < 4; i++) dst[i] = src[i];
    }
    {
        int r = t128 >> 1, cb = (t128 & 1) * 64;
        int rr = wg * 64 + r;
        const float* src = rel + (size_t)rr * HD_ + cb;
        char* dst = smraw + ATT2_KS + wg * ATT_WGS + r * 272 + cb * 2;
        #pragma unroll
        for (int i = 0; i < 8; i++) {
            float4 f0 = *(const float4*)(src + i * 8);
            float4 f1 = *(const float4*)(src + i * 8 + 4);
            uint4 st;
            st.x = packbf(f0.x, f0.y); st.y = packbf(f0.z, f0.w);
            st.z = packbf(f1.x, f1.y); st.w = packbf(f1.z, f1.w);
            *(uint4*)(dst + i * 16) = st;
        }
    }
    __syncthreads();

    uint32_t sQ = smem_to_u32(smraw + ATT2_QS);
    uint32_t aQAddr = sQ + (ww * 16 + (lane & 15)) * 272 + (lane >> 4) * 16;
    uint32_t qf[8][4];
    #pragma unroll
    for (int ks = 0; ks < 8; ks++)
        ldsm4(qf[ks][0], qf[ks][1], qf[ks][2], qf[ks][3], aQAddr + ks * 32);

    int bRow = ((lane >> 4) & 1) * 8 + (lane & 7);
    int bColB = ((lane >> 3) & 1) * 16;
    uint32_t sKS = smem_to_u32(smraw + ATT2_KS) + wg * ATT_WGS;
    uint32_t sVS = smem_to_u32(smraw + ATT2_VS) + wg * ATT_WGS;

    int r0 = lane >> 2, cA = (lane & 3) * 2;
    int m0row = ww * 16 + r0;

    {
        float c[8][4];
        #pragma unroll
        for (int nt = 0; nt < 8; nt++)
            #pragma unroll
            for (int j = 0; j < 4; j++) c[nt][j] = 0.f;
        #pragma unroll
        for (int ks = 0; ks < 8; ks++) {
            uint32_t bfd[8][2];
            #pragma unroll
            for (int np = 0; np < 4; np++) {
                uint32_t x0, x1, x2, x3;
                ldsm4(x0, x1, x2, x3,
                      sKS + (np * 16 + bRow) * 272 + bColB + ks * 32);
                bfd[np * 2][0] = x0;     bfd[np * 2][1] = x1;
                bfd[np * 2 + 1][0] = x2; bfd[np * 2 + 1][1] = x3;
            }
            #pragma unroll
            for (int nt = 0; nt < 8; nt++)
                mma16816(c[nt], qf[ks], bfd[nt]);
        }
        #pragma unroll
        for (int nt = 0; nt < 8; nt++) {
            int col = wg * 64 + nt * 8 + cA;
            Rl[m0row * 132 + col]           = c[nt][0];
            Rl[m0row * 132 + col + 1]       = c[nt][1];
            Rl[(m0row + 8) * 132 + col]     = c[nt][2];
            Rl[(m0row + 8) * 132 + col + 1] = c[nt][3];
        }
    }
    {
        int m = tid >> 2, l4 = tid & 3;
        const float* rrow = rel + (size_t)128 * HD_ + l4 * 32;
        const __nv_bfloat16* qrow = Qs + m * 136 + l4 * 32;
        float s = 0.f;
        #pragma unroll
        for (int i = 0; i < 32; i++)
            s = fmaf(__bfloat162float(qrow[i]), rrow[i], s);
        s += __shfl_xor_sync(0xffffffffu, s, 1);
        s += __shfl_xor_sync(0xffffffffu, s, 2);
        if (l4 == 0) Rl[m * 132 + 128] = s;
    }
    __syncthreads();

    float m_run0 = -1e30f, m_run1 = -1e30f;
    float l_run0 = 0.f, l_run1 = 0.f;
    float ctx[16][4];
    #pragma unroll
    for (int nt = 0; nt < 16; nt++)
        #pragma unroll
        for (int j = 0; j < 4; j++) ctx[nt][j] = 0.f;

    int pos0 = (ls0 + m0row) >> 1;
    int pos1 = (ls0 + m0row + 8) >> 1;
    int vRow = lane & 15;
    int vColB = (lane >> 4) * 16;

    int ldr = t128 >> 1, ldc = (t128 & 1) * 64;
    {
        int j0 = (0 * 2 + wg) * 64;
        const __nv_bfloat16* ks = kg + (size_t)(b * S_ + j0 + ldr) * HD_ + ldc;
        const __nv_bfloat16* vs = vg + (size_t)(b * S_ + j0 + ldr) * HD_ + ldc;
        uint32_t kd = sKS + ldr * 272 + ldc * 2;
        uint32_t vd = sVS + ldr * 272 + ldc * 2;
        #pragma unroll
        for (int i = 0; i < 8; i++) {
            CPASYNC16(kd + i * 16, ks + i * 8);
            CPASYNC16(vd + i * 16, vs + i * 8);
        }
        CPCOMMIT();
    }

    for (int t = 0; t < 8; t++) {
        if (t + 1 < 8) {
            int j0 = ((t + 1) * 2 + wg) * 64;
            uint32_t boff = ((t + 1) & 1) * ATT_BUFS;
            const __nv_bfloat16* ks = kg + (size_t)(b * S_ + j0 + ldr) * HD_ + ldc;
            const __nv_bfloat16* vs = vg + (size_t)(b * S_ + j0 + ldr) * HD_ + ldc;
            uint32_t kd = sKS + boff + ldr * 272 + ldc * 2;
            uint32_t vd = sVS + boff + ldr * 272 + ldc * 2;
            #pragma unroll
            for (int i = 0; i < 8; i++) {
                CPASYNC16(kd + i * 16, ks + i * 8);
                CPASYNC16(vd + i * 16, vs + i * 8);
            }
            CPCOMMIT();
            CPWAIT1();
        } else {
            CPWAIT0();
        }
        __syncthreads();
        uint32_t kbuf = sKS + (t & 1) * ATT_BUFS;
        uint32_t vbuf = sVS + (t & 1) * ATT_BUFS;
        int j0 = (t * 2 + wg) * 64;

        float c[8][4];
        #pragma unroll
        for (int nt = 0; nt < 8; nt++)
            #pragma unroll
            for (int j = 0; j < 4; j++) c[nt][j] = 0.f;
        #pragma unroll
        for (int ks = 0; ks < 8; ks++) {
            uint32_t bfd[8][2];
            #pragma unroll
            for (int np = 0; np < 4; np++) {
                uint32_t x0, x1, x2, x3;
                ldsm4(x0, x1, x2, x3,
                      kbuf + (np * 16 + bRow) * 272 + bColB + ks * 32);
                bfd[np * 2][0] = x0;     bfd[np * 2][1] = x1;
                bfd[np * 2 + 1][0] = x2; bfd[np * 2 + 1][1] = x3;
            }
            #pragma unroll
            for (int nt = 0; nt < 8; nt++)
                mma16816(c[nt], qf[ks], bfd[nt]);
        }
        #pragma unroll
        for (int nt = 0; nt < 8; nt++) {
            int j = j0 + nt * 8 + cA;
            int i00 = min(max(j - pos0, -64), 64) + 64;
            int i01 = min(max(j + 1 - pos0, -64), 64) + 64;
            int i10 = min(max(j - pos1, -64), 64) + 64;
            int i11 = min(max(j + 1 - pos1, -64), 64) + 64;
            c[nt][0] += Rl[m0row * 132 + i00];
            c[nt][1] += Rl[m0row * 132 + i01];
            c[nt][2] += Rl[(m0row + 8) * 132 + i10];
            c[nt][3] += Rl[(m0row + 8) * 132 + i11];
        }
        float mx0 = -1e30f, mx1 = -1e30f;
        #pragma unroll
        for (int nt = 0; nt < 8; nt++) {
            mx0 = fmaxf(mx0, fmaxf(c[nt][0], c[nt][1]));
            mx1 = fmaxf(mx1, fmaxf(c[nt][2], c[nt][3]));
        }
        mx0 = fmaxf(mx0, __shfl_xor_sync(0xffffffffu, mx0, 1));
        mx0 = fmaxf(mx0, __shfl_xor_sync(0xffffffffu, mx0, 2));
        mx1 = fmaxf(mx1, __shfl_xor_sync(0xffffffffu, mx1, 1));
        mx1 = fmaxf(mx1, __shfl_xor_sync(0xffffffffu, mx1, 2));
        float mn0 = fmaxf(m_run0, mx0), mn1 = fmaxf(m_run1, mx1);
        float sc0 = __expf(m_run0 - mn0), sc1 = __expf(m_run1 - mn1);
        m_run0 = mn0; m_run1 = mn1;
        float rs0 = 0.f, rs1 = 0.f;
        #pragma unroll
        for (int nt = 0; nt < 8; nt++) {
            c[nt][0] = __expf(c[nt][0] - mn0); rs0 += c[nt][0];
            c[nt][1] = __expf(c[nt][1] - mn0); rs0 += c[nt][1];
            c[nt][2] = __expf(c[nt][2] - mn1); rs1 += c[nt][2];
            c[nt][3] = __expf(c[nt][3] - mn1); rs1 += c[nt][3];
        }
        rs0 += __shfl_xor_sync(0xffffffffu, rs0, 1);
        rs0 += __shfl_xor_sync(0xffffffffu, rs0, 2);
        rs1 += __shfl_xor_sync(0xffffffffu, rs1, 1);
        rs1 += __shfl_xor_sync(0xffffffffu, rs1, 2);
        l_run0 = l_run0 * sc0 + rs0;
        l_run1 = l_run1 * sc1 + rs1;
        #pragma unroll
        for (int nt = 0; nt < 16; nt++) {
            ctx[nt][0] *= sc0; ctx[nt][1] *= sc0;
            ctx[nt][2] *= sc1; ctx[nt][3] *= sc1;
        }
        uint32_t pf[4][4];
        #pragma unroll
        for (int k2 = 0; k2 < 4; k2++) {
            pf[k2][0] = packbf(c[2 * k2][0], c[2 * k2][1]);
            pf[k2][1] = packbf(c[2 * k2][2], c[2 * k2][3]);
            pf[k2][2] = packbf(c[2 * k2 + 1][0], c[2 * k2 + 1][1]);
            pf[k2][3] = packbf(c[2 * k2 + 1][2], c[2 * k2 + 1][3]);
        }
        #pragma unroll
        for (int k2 = 0; k2 < 4; k2++) {
            #pragma unroll
            for (int dp = 0; dp < 8; dp++) {
                uint32_t x0, x1, x2, x3;
                ldsm4t(x0, x1, x2, x3,
                       vbuf + (k2 * 16 + vRow) * 272 + dp * 32 + vColB);
                uint32_t b0[2] = {x0, x1};
                uint32_t b1[2] = {x2, x3};
                mma16816(ctx[2 * dp], pf[k2], b0);
                mma16816(ctx[2 * dp + 1], pf[k2], b1);
            }
        }
        __syncthreads();
    }

    if ((lane & 3) == 0) {
        sM[wg * 64 + m0row] = m_run0;     sL[wg * 64 + m0row] = l_run0;
        sM[wg * 64 + m0row + 8] = m_run1; sL[wg * 64 + m0row + 8] = l_run1;
    }
    __syncthreads();
    float mo0 = sM[(1 - wg) * 64 + m0row];
    float mo1 = sM[(1 - wg) * 64 + m0row + 8];
    float lo0 = sL[(1 - wg) * 64 + m0row];
    float lo1 = sL[(1 - wg) * 64 + m0row + 8];
    float M0 = fmaxf(m_run0, mo0), M1 = fmaxf(m_run1, mo1);
    float s0 = __expf(m_run0 - M0), s1 = __expf(m_run1 - M1);
    float lt0 = l_run0 * s0 + lo0 * __expf(mo0 - M0);
    float lt1 = l_run1 * s1 + lo1 * __expf(mo1 - M1);
    #pragma unroll
    for (int nt = 0; nt < 16; nt++) {
        ctx[nt][0] *= s0; ctx[nt][1] *= s0;
        ctx[nt][2] *= s1; ctx[nt][3] *= s1;
    }
    __syncthreads();
    if (wg == 1) {
        #pragma unroll
        for (int nt = 0; nt < 16; nt++) {
            int col = nt * 8 + cA;
            Rl[m0row * 132 + col]           = ctx[nt][0];
            Rl[m0row * 132 + col + 1]       = ctx[nt][1];
            Rl[(m0row + 8) * 132 + col]     = ctx[nt][2];
            Rl[(m0row + 8) * 132 + col + 1] = ctx[nt][3];
        }
    }
    __syncthreads();
    if (wg == 0) {
        float inv0 = 1.f / lt0, inv1 = 1.f / lt1;
        #pragma unroll
        for (int nt = 0; nt < 16; nt++) {
            int col = nt * 8 + cA;
            float v0 = (ctx[nt][0] + Rl[m0row * 132 + col]) * inv0;
            float v1 = (ctx[nt][1] + Rl[m0row * 132 + col + 1]) * inv0;
            float v2 = (ctx[nt][2] + Rl[(m0row + 8) * 132 + col]) * inv1;
            float v3 = (ctx[nt][3] + Rl[(m0row + 8) * 132 + col + 1]) * inv1;
            *(uint32_t*)(ctxg + (size_t)(gs0 + m0row) * HD_ + col) = packbf(v0, v1);
            *(uint32_t*)(ctxg + (size_t)(gs0 + m0row + 8) * HD_ + col) = packbf(v2, v3);
        }
    }
}

// ---------------------------------------------------------------------------
// Host launcher
// ---------------------------------------------------------------------------
extern "C" void kernel_launch(void* const* d_in, const int* in_sizes, int n_in,
                              void* d_out, int out_size) {
    const float* src  = (const float*)d_in[0];
    const float* ln1w = (const float*)d_in[1];
    const float* ln1b = (const float*)d_in[2];
    const float* ln2w = (const float*)d_in[3];
    const float* ln2b = (const float*)d_in[4];
    const float* agw  = (const float*)d_in[5];
    const float* qw   = (const float*)d_in[6];
    const float* qb   = (const float*)d_in[7];
    const float* kw   = (const float*)d_in[8];
    const float* kb   = (const float*)d_in[9];
    const float* vw   = (const float*)d_in[10];
    const float* vb   = (const float*)d_in[11];
    const float* ow   = (const float*)d_in[12];
    const float* ob   = (const float*)d_in[13];
    const float* rel  = (const float*)d_in[14];
    const float* fgw  = (const float*)d_in[15];
    const float* w1   = (const float*)d_in[16];
    const float* b1   = (const float*)d_in[17];
    const float* w2   = (const float*)d_in[18];
    const float* b2   = (const float*)d_in[19];
    float* out = (float*)d_out;

    float *gwa, *gwf, *kvb;
    int *cnta, *cntf, *lista, *listf;
    __nv_bfloat16 *xnbf, *xn2bf, *qbf, *kvbf, *ctxbf, *hbf, *yabf, *wbf;
    cudaGetSymbolAddress((void**)&gwa,   g_gwa);
    cudaGetSymbolAddress((void**)&gwf,   g_gwf);
    cudaGetSymbolAddress((void**)&kvb,   g_kvb);
    cudaGetSymbolAddress((void**)&cnta,  g_cnt_a);
    cudaGetSymbolAddress((void**)&cntf,  g_cnt_f);
    cudaGetSymbolAddress((void**)&lista, g_list_a);
    cudaGetSymbolAddress((void**)&listf, g_list_f);
    cudaGetSymbolAddress((void**)&xnbf,  g_xn_bf);
    cudaGetSymbolAddress((void**)&xn2bf, g_xn2_bf);
    cudaGetSymbolAddress((void**)&qbf,   g_q_bf);
    cudaGetSymbolAddress((void**)&kvbf,  g_kv_bf);
    cudaGetSymbolAddress((void**)&ctxbf, g_ctx_bf);
    cudaGetSymbolAddress((void**)&hbf,   g_h_bf);
    cudaGetSymbolAddress((void**)&yabf,  g_ya_bf);
    cudaGetSymbolAddress((void**)&wbf,   g_wbf);

    __nv_bfloat16* w1t  = wbf + WSEG_W1;
    __nv_bfloat16* w2t  = wbf + WSEG_W2;
    __nv_bfloat16* qwt  = wbf + WSEG_QW;
    __nv_bfloat16* owt  = wbf + WSEG_OW;
    __nv_bfloat16* kvwt = wbf + WSEG_KW;

    static cudaStream_t s1 = nullptr;
    static cudaEvent_t ev_fork = nullptr, ev_join = nullptr;
    static bool attr_set = []() {
        cudaFuncSetAttribute(attn_mma_k,
                             cudaFuncAttributeMaxDynamicSharedMemorySize,
                             ATT2_SMEM);
        cudaFuncSetAttribute(qkv_k,
                             cudaFuncAttributeMaxDynamicSharedMemorySize, GEMM_SMEM_BM64);
        cudaFuncSetAttribute(mmasync_gemm_k<HD_, 128, false, false, true, true, false>,
                             cudaFuncAttributeMaxDynamicSharedMemorySize, GEMM_SMEM_BM128);
        cudaFuncSetAttribute(mmasync_gemm_k<D_, 128, true, true, false, true, false>,
                             cudaFuncAttributeMaxDynamicSharedMemorySize, GEMM_SMEM_BM128);
        cudaFuncSetAttribute(mmasync_gemm_k<FH_, 128, false, false, true, false, true>,
                             cudaFuncAttributeMaxDynamicSharedMemorySize, GEMM_SMEM_BM128);
        return true;
    }();
    (void)attr_set;
    if (!s1) {
        cudaStreamCreateWithFlags(&s1, cudaStreamNonBlocking);
        cudaEventCreateWithFlags(&ev_fork, cudaEventDisableTiming);
        cudaEventCreateWithFlags(&ev_join, cudaEventDisableTiming);
    }

    // fork: weight conversion on side stream, concurrent with setup+ln1
    cudaEventRecord(ev_fork, 0);
    cudaStreamWaitEvent(s1, ev_fork, 0);
    conv_all_k<<<(WSEG_END / 4 + 255) / 256, 256, 0, s1>>>(w1, w2, qw, ow, kw, vw);
    cudaEventRecord(ev_join, s1);

    setup_k<<<(2 * CAP_) / 256, 256>>>(kb, vb);
    ln1_k<<<NTOK_, 256>>>(src, ln1w, ln1b, agw, xnbf);

    cudaStreamWaitEvent(0, ev_join, 0);

    // fused K/V + Q projection
    qkv_k<<<dim3(1, NTOK_ / 64, 2 + EA_), 256, GEMM_SMEM_BM64>>>(
        xnbf, kvwt, qwt, kvb, qb, kvbf, qbf, lista, cnta,
        0.08838834764831845f);

    // flash attention (double-buffered)
    attn_mma_k<<<NTS_ / 64, 256, ATT2_SMEM>>>(
        qbf, kvbf, kvbf + (size_t)NTOK_ * HD_, rel, ctxbf);

    // per-expert output projection, gated (bf16 out), BM=128 (halves ow re-reads)
    mmasync_gemm_k<HD_, 128, false, false, true, true, false>
        <<<dim3(D_ / 128, CAP_ / 128, EA_), 256, GEMM_SMEM_BM128>>>(
        ctxbf, owt, ob, D_, (void*)yabf, D_, 0,
        lista, cnta, gwa, 1.f);

    // residual + LN2 + FFN router; residual -> out
    combine_ln2_k<<<NTOK_, 256>>>(src, yabf, ln2w, ln2b, fgw, out, xn2bf);

    // FFN, BM=128: w1 (relu -> bf16 h), w2 accumulates into out (red.v2)
    mmasync_gemm_k<D_, 128, true, true, false, true, false>
        <<<dim3(FH_ / 128, CAP_ / 128, EF_), 256, GEMM_SMEM_BM128>>>(
        xn2bf, w1t, b1, FH_, (void*)hbf, FH_, 0,
        listf, cntf, nullptr, 1.f);
    mmasync_gemm_k<FH_, 128, false, false, true, false, true>
        <<<dim3(D_ / 128, CAP_ / 128, EF_), 256, GEMM_SMEM_BM128>>>(
        hbf, w2t, b2, D_, (void*)out, D_, 0,
        listf, cntf, gwf, 1.f);
}